// round 1
// baseline (speedup 1.0000x reference)
#include <cuda_runtime.h>
#include <math.h>

#define BATCH 8
#define CIN   256
#define NPOS  1568
#define NH    4
#define DH    128
#define O3    1536   // 3 * NH * DH

// Scratch (allocation-free rule: device globals). ~77 MB total, fits in HBM easily,
// and the hot working set fits in L2 (126 MB).
__device__ float g_q[BATCH*NH*DH*NPOS];   // [bh][d][n], pre-scaled
__device__ float g_k[BATCH*NH*DH*NPOS];   // [bh][d][n], k + emb folded in
__device__ float g_v[(size_t)BATCH*NH*NPOS*DH]; // [bh][n][d]

// ---------------------------------------------------------------------------
// Kernel A: QKV projection GEMM.  Per batch b:  W_qkv[1536,256] @ fmap_b[256,1568]
// Tiles: 64x64, BK=16, 256 threads, 4x4 per thread.
// Epilogue scatters into q/k/v scratch with scale & positional embedding fused.
// ---------------------------------------------------------------------------
__global__ __launch_bounds__(256) void qkv_kernel(
    const float* __restrict__ fmap, const float* __restrict__ Wq,
    const float* __restrict__ pf, const float* __restrict__ ph,
    const float* __restrict__ pw)
{
    __shared__ float As[16][68];   // [k][o], pad 68 -> <=2-way conflicts
    __shared__ float Bs[16][64];   // [k][pos]

    const int tid = threadIdx.x;
    const int tx = tid & 15, ty = tid >> 4;
    const int pbase = blockIdx.x * 64;   // pos tile (25 tiles, last partial)
    const int obase = blockIdx.y * 64;   // output-channel tile (24 tiles)
    const int b     = blockIdx.z;

    float acc[4][4];
#pragma unroll
    for (int r=0;r<4;r++)
#pragma unroll
        for (int c=0;c<4;c++) acc[r][c] = 0.f;

    for (int k0 = 0; k0 < CIN; k0 += 16) {
        {   // load A tile 64(o) x 16(k); global reads 16-float rows (coalesced-ish, L2-hot)
            int k_l = tid & 15, o_l = tid >> 4;
#pragma unroll
            for (int p=0;p<4;p++)
                As[k_l][o_l + p*16] = Wq[(obase + o_l + p*16)*CIN + k0 + k_l];
        }
        {   // load B tile 16(k) x 64(pos); fully coalesced
            int pos_l = tid & 63, k_l = tid >> 6;
#pragma unroll
            for (int p=0;p<4;p++) {
                int kk = k_l + p*4;
                int pos = pbase + pos_l;
                Bs[kk][pos_l] = (pos < NPOS) ? fmap[(b*CIN + k0 + kk)*NPOS + pos] : 0.f;
            }
        }
        __syncthreads();
#pragma unroll
        for (int kk=0; kk<16; kk++) {
            float4 av = *(const float4*)&As[kk][ty*4];
            float4 bv = *(const float4*)&Bs[kk][tx*4];
            acc[0][0] += av.x*bv.x; acc[0][1] += av.x*bv.y; acc[0][2] += av.x*bv.z; acc[0][3] += av.x*bv.w;
            acc[1][0] += av.y*bv.x; acc[1][1] += av.y*bv.y; acc[1][2] += av.y*bv.z; acc[1][3] += av.y*bv.w;
            acc[2][0] += av.z*bv.x; acc[2][1] += av.z*bv.y; acc[2][2] += av.z*bv.z; acc[2][3] += av.z*bv.w;
            acc[3][0] += av.w*bv.x; acc[3][1] += av.w*bv.y; acc[3][2] += av.w*bv.z; acc[3][3] += av.w*bv.w;
        }
        __syncthreads();
    }

    const float scl = 0.08838834764831845f;  // 128^-0.5
#pragma unroll
    for (int r=0;r<4;r++) {
        int o    = obase + ty*4 + r;
        int sec  = o >> 9;          // 0=q 1=k 2=v  (uniform per block: 64-row tiles align)
        int head = (o >> 7) & 3;
        int d    = o & 127;
        int bh   = b*NH + head;
#pragma unroll
        for (int c=0;c<4;c++) {
            int pos = pbase + tx*4 + c;
            if (pos >= NPOS) continue;
            float v = acc[r][c];
            if (sec == 0) {
                g_q[(bh*DH + d)*NPOS + pos] = v * scl;
            } else if (sec == 1) {
                int f_ = pos / 196; int rem = pos - f_*196;
                int h_ = rem / 14;  int w_  = rem - h_*14;
                g_k[(bh*DH + d)*NPOS + pos] =
                    v + pf[f_*DH + d] + ph[h_*DH + d] + pw[w_*DH + d];
            } else {
                g_v[(size_t)(bh*NPOS + pos)*DH + d] = v;
            }
        }
    }
}

// ---------------------------------------------------------------------------
// Kernel B: flash attention, fp32.  Block = 64 queries x (stream 64-key tiles).
// 256 threads (16x16).  S: thread owns 4 rows x 4 cols. O: 4 rows x 8 d-cols.
// smem: Qs[128][64] (d-major), Ks[128][64] (reused as Ps[64][68]), Vs[64][132].
// All smem access patterns are bank-conflict-free (checked per warp).
// ---------------------------------------------------------------------------
__global__ __launch_bounds__(256, 2) void attn_kernel(float* __restrict__ out)
{
    extern __shared__ float sm[];
    float* Qs = sm;            // 128*64
    float* Ks = sm + 8192;     // 128*64, later reused as Ps (64*68 <= 8192)
    float* Vs = sm + 16384;    // 64*132
    float* Ps = Ks;

    const int tid = threadIdx.x;
    const int tx = tid & 15, ty = tid >> 4;
    const int qt = blockIdx.x;       // 25 query tiles
    const int bh = blockIdx.y;       // 32 (b,h)
    const int qbase = qt * 64;

    const float* qp = g_q + (size_t)bh * DH * NPOS;
    const float* kp = g_k + (size_t)bh * DH * NPOS;
    const float* vp = g_v + (size_t)bh * NPOS * DH;

    {   // load Q tile [d][i], vectorized over i
        int d0 = tid >> 4; int i = (tid & 15) * 4;
        bool ok = (qbase + i) < NPOS;
#pragma unroll
        for (int p=0;p<8;p++) {
            float4 v = make_float4(0.f,0.f,0.f,0.f);
            if (ok) v = *(const float4*)&qp[(d0 + p*16)*NPOS + qbase + i];
            *(float4*)&Qs[(d0 + p*16)*64 + i] = v;
        }
    }

    float m_i[4], l_i[4], O[4][8];
#pragma unroll
    for (int r=0;r<4;r++){
        m_i[r] = -1e30f; l_i[r] = 0.f;
#pragma unroll
        for (int k=0;k<8;k++) O[r][k] = 0.f;
    }

    for (int ktile = 0; ktile < 25; ktile++) {
        const int kb = ktile * 64;
        __syncthreads();   // previous tile's PV readers done before overwrite
        {   // load K tile [d][j]
            int d0 = tid >> 4; int j = (tid & 15) * 4;
            bool ok = (kb + j) < NPOS;
#pragma unroll
            for (int p=0;p<8;p++) {
                float4 v = make_float4(0.f,0.f,0.f,0.f);
                if (ok) v = *(const float4*)&kp[(d0 + p*16)*NPOS + kb + j];
                *(float4*)&Ks[(d0 + p*16)*64 + j] = v;
            }
        }
        {   // load V tile [j][d]
            int j0 = tid >> 5; int d = (tid & 31) * 4;
#pragma unroll
            for (int p=0;p<8;p++) {
                int jj = j0 + p*8;
                float4 v = make_float4(0.f,0.f,0.f,0.f);
                if (kb + jj < NPOS) v = *(const float4*)&vp[(size_t)(kb + jj)*DH + d];
                *(float4*)&Vs[jj*132 + d] = v;
            }
        }
        __syncthreads();

        // ---- S = Q K'^T (64x64) ----
        float S[4][4];
#pragma unroll
        for (int r=0;r<4;r++)
#pragma unroll
            for (int c=0;c<4;c++) S[r][c] = 0.f;
#pragma unroll 16
        for (int d=0; d<128; d++) {
            float4 qv = *(const float4*)&Qs[d*64 + ty*4];
            float4 kv = *(const float4*)&Ks[d*64 + tx*4];
            S[0][0] += qv.x*kv.x; S[0][1] += qv.x*kv.y; S[0][2] += qv.x*kv.z; S[0][3] += qv.x*kv.w;
            S[1][0] += qv.y*kv.x; S[1][1] += qv.y*kv.y; S[1][2] += qv.y*kv.z; S[1][3] += qv.y*kv.w;
            S[2][0] += qv.z*kv.x; S[2][1] += qv.z*kv.y; S[2][2] += qv.z*kv.z; S[2][3] += qv.z*kv.w;
            S[3][0] += qv.w*kv.x; S[3][1] += qv.w*kv.y; S[3][2] += qv.w*kv.z; S[3][3] += qv.w*kv.w;
        }
        if (kb + 64 > NPOS) {   // mask tail keys
#pragma unroll
            for (int c=0;c<4;c++)
                if (kb + tx*4 + c >= NPOS) {
                    S[0][c] = -1e30f; S[1][c] = -1e30f; S[2][c] = -1e30f; S[3][c] = -1e30f;
                }
        }

        // ---- online softmax (row reduce across the 16 tx lanes) ----
        float P[4][4];
#pragma unroll
        for (int r=0;r<4;r++) {
            float rm = fmaxf(fmaxf(S[r][0],S[r][1]), fmaxf(S[r][2],S[r][3]));
            rm = fmaxf(rm, __shfl_xor_sync(0xffffffffu, rm, 1));
            rm = fmaxf(rm, __shfl_xor_sync(0xffffffffu, rm, 2));
            rm = fmaxf(rm, __shfl_xor_sync(0xffffffffu, rm, 4));
            rm = fmaxf(rm, __shfl_xor_sync(0xffffffffu, rm, 8));
            float mn   = fmaxf(m_i[r], rm);
            float corr = __expf(m_i[r] - mn);
            m_i[r] = mn;
            float rs = 0.f;
#pragma unroll
            for (int c=0;c<4;c++) { P[r][c] = __expf(S[r][c] - mn); rs += P[r][c]; }
            rs += __shfl_xor_sync(0xffffffffu, rs, 1);
            rs += __shfl_xor_sync(0xffffffffu, rs, 2);
            rs += __shfl_xor_sync(0xffffffffu, rs, 4);
            rs += __shfl_xor_sync(0xffffffffu, rs, 8);
            l_i[r] = l_i[r]*corr + rs;
#pragma unroll
            for (int k=0;k<8;k++) O[r][k] *= corr;
        }

        __syncthreads();   // all Ks reads done -> safe to reuse as Ps
#pragma unroll
        for (int r=0;r<4;r++)
            *(float4*)&Ps[(ty*4+r)*68 + tx*4] = make_float4(P[r][0],P[r][1],P[r][2],P[r][3]);
        __syncthreads();

        // ---- O += P V (64x128) ----
#pragma unroll 8
        for (int j=0;j<64;j++) {
            float4 v0 = *(const float4*)&Vs[j*132 + tx*4];
            float4 v1 = *(const float4*)&Vs[j*132 + 64 + tx*4];
#pragma unroll
            for (int r=0;r<4;r++) {
                float pv = Ps[(ty*4+r)*68 + j];   // broadcast within warp
                O[r][0] += pv*v0.x; O[r][1] += pv*v0.y; O[r][2] += pv*v0.z; O[r][3] += pv*v0.w;
                O[r][4] += pv*v1.x; O[r][5] += pv*v1.y; O[r][6] += pv*v1.z; O[r][7] += pv*v1.w;
            }
        }
    }

    // ---- finalize + write out in [b, h*128+d, n] layout (L2 merges sectors) ----
    const int b = bh >> 2, head = bh & 3;
    const size_t ch0 = (size_t)b*512 + head*128;
#pragma unroll
    for (int r=0;r<4;r++) {
        int i = qbase + ty*4 + r;
        if (i >= NPOS) continue;
        float inv = 1.0f / l_i[r];
#pragma unroll
        for (int k=0;k<4;k++) {
            out[(ch0 + tx*4 + k)*NPOS + i]      = O[r][k]   * inv;
            out[(ch0 + 64 + tx*4 + k)*NPOS + i] = O[r][4+k] * inv;
        }
    }
}

// ---------------------------------------------------------------------------
extern "C" void kernel_launch(void* const* d_in, const int* in_sizes, int n_in,
                              void* d_out, int out_size)
{
    const float* fmap = (const float*)d_in[0];
    const float* Wq   = (const float*)d_in[1];
    const float* pf   = (const float*)d_in[2];
    const float* ph   = (const float*)d_in[3];
    const float* pw   = (const float*)d_in[4];
    float* out = (float*)d_out;

    dim3 gA(25, 24, BATCH);   // pos-tiles, o-tiles, batch
    qkv_kernel<<<gA, 256>>>(fmap, Wq, pf, ph, pw);

    const size_t smemB = (size_t)24832 * sizeof(float);   // ~97 KB
    cudaFuncSetAttribute(attn_kernel, cudaFuncAttributeMaxDynamicSharedMemorySize,
                         (int)smemB);
    dim3 gB(25, 32);          // query-tiles, (b,h)
    attn_kernel<<<gB, 256, smemB>>>(out);
}

// round 2
// speedup vs baseline: 1.8247x; 1.8247x over previous
#include <cuda_runtime.h>
#include <math.h>
#include <stdint.h>

#define BATCH 8
#define CIN   256
#define NPOS  1568
#define NH    4
#define DH    128

// Scratch: [bh][token][d], values pre-rounded to tf32 bit patterns.
__device__ float g_q[BATCH*NH*NPOS*DH];   // pre-scaled
__device__ float g_k[BATCH*NH*NPOS*DH];   // k + positional emb folded in
__device__ float g_v[BATCH*NH*NPOS*DH];

__device__ __forceinline__ float to_tf32(float x) {
    uint32_t u;
    asm("cvt.rna.tf32.f32 %0, %1;" : "=r"(u) : "f"(x));
    return __uint_as_float(u);
}

__device__ __forceinline__ void mma_tf32(float c[4],
        uint32_t a0, uint32_t a1, uint32_t a2, uint32_t a3,
        uint32_t b0, uint32_t b1) {
    asm volatile(
        "mma.sync.aligned.m16n8k8.row.col.f32.tf32.tf32.f32 "
        "{%0,%1,%2,%3}, {%4,%5,%6,%7}, {%8,%9}, {%0,%1,%2,%3};\n"
        : "+f"(c[0]), "+f"(c[1]), "+f"(c[2]), "+f"(c[3])
        : "r"(a0), "r"(a1), "r"(a2), "r"(a3), "r"(b0), "r"(b1));
}

// ---------------------------------------------------------------------------
// Kernel A: QKV projection GEMM (fp32 FFMA, unchanged math).
// Epilogue: scale Q, fold emb into K, round all to tf32, store [bh][token][d].
// ---------------------------------------------------------------------------
__global__ __launch_bounds__(256) void qkv_kernel(
    const float* __restrict__ fmap, const float* __restrict__ Wq,
    const float* __restrict__ pf, const float* __restrict__ ph,
    const float* __restrict__ pw)
{
    __shared__ float As[16][68];
    __shared__ float Bs[16][64];

    const int tid = threadIdx.x;
    const int tx = tid & 15, ty = tid >> 4;
    const int pbase = blockIdx.x * 64;
    const int obase = blockIdx.y * 64;
    const int b     = blockIdx.z;

    float acc[4][4];
#pragma unroll
    for (int r=0;r<4;r++)
#pragma unroll
        for (int c=0;c<4;c++) acc[r][c] = 0.f;

    for (int k0 = 0; k0 < CIN; k0 += 16) {
        {
            int k_l = tid & 15, o_l = tid >> 4;
#pragma unroll
            for (int p=0;p<4;p++)
                As[k_l][o_l + p*16] = Wq[(obase + o_l + p*16)*CIN + k0 + k_l];
        }
        {
            int pos_l = tid & 63, k_l = tid >> 6;
#pragma unroll
            for (int p=0;p<4;p++) {
                int kk = k_l + p*4;
                int pos = pbase + pos_l;
                Bs[kk][pos_l] = (pos < NPOS) ? fmap[(b*CIN + k0 + kk)*NPOS + pos] : 0.f;
            }
        }
        __syncthreads();
#pragma unroll
        for (int kk=0; kk<16; kk++) {
            float4 av = *(const float4*)&As[kk][ty*4];
            float4 bv = *(const float4*)&Bs[kk][tx*4];
            acc[0][0] += av.x*bv.x; acc[0][1] += av.x*bv.y; acc[0][2] += av.x*bv.z; acc[0][3] += av.x*bv.w;
            acc[1][0] += av.y*bv.x; acc[1][1] += av.y*bv.y; acc[1][2] += av.y*bv.z; acc[1][3] += av.y*bv.w;
            acc[2][0] += av.z*bv.x; acc[2][1] += av.z*bv.y; acc[2][2] += av.z*bv.z; acc[2][3] += av.z*bv.w;
            acc[3][0] += av.w*bv.x; acc[3][1] += av.w*bv.y; acc[3][2] += av.w*bv.z; acc[3][3] += av.w*bv.w;
        }
        __syncthreads();
    }

    const float scl = 0.08838834764831845f;  // 128^-0.5
#pragma unroll
    for (int r=0;r<4;r++) {
        int o    = obase + ty*4 + r;
        int sec  = o >> 9;          // 0=q 1=k 2=v (uniform per 64-row tile)
        int head = (o >> 7) & 3;
        int d    = o & 127;
        int bh   = b*NH + head;
#pragma unroll
        for (int c=0;c<4;c++) {
            int pos = pbase + tx*4 + c;
            if (pos >= NPOS) continue;
            float v = acc[r][c];
            size_t idx = (size_t)(bh*NPOS + pos)*DH + d;
            if (sec == 0) {
                g_q[idx] = to_tf32(v * scl);
            } else if (sec == 1) {
                int f_ = pos / 196; int rem = pos - f_*196;
                int h_ = rem / 14;  int w_  = rem - h_*14;
                g_k[idx] = to_tf32(v + pf[f_*DH + d] + ph[h_*DH + d] + pw[w_*DH + d]);
            } else {
                g_v[idx] = to_tf32(v);
            }
        }
    }
}

// ---------------------------------------------------------------------------
// Kernel B: flash attention with tf32 mma.sync.m16n8k8.
// 128 threads (4 warps). Br=64, Bc=64, d=128. Warp w owns S-rows [16w,16w+16).
// smem: Qs/Ks/Vs [64][132] fp32(tf32). Ps[64][68] overlays Ks. Od[128][68]
// overlays Ks+Vs for the transposed, coalesced epilogue.
// ---------------------------------------------------------------------------
__global__ __launch_bounds__(128, 2) void attn_kernel(float* __restrict__ out)
{
    extern __shared__ float sm[];
    float* Qs = sm;                  // 64*132
    float* Ks = sm + 8448;           // 64*132
    float* Vs = sm + 16896;          // 64*132
    float* Ps = Ks;                  // 64*68 overlay
    float* Od = Ks;                  // 128*68 overlay (Ks+Vs region)

    const int tid  = threadIdx.x;
    const int lane = tid & 31, w = tid >> 5;
    const int gid  = lane >> 2, tig = lane & 3;
    const int qt = blockIdx.x, bh = blockIdx.y;
    const int qbase = qt * 64;
    const int row0 = w*16 + gid;     // warp-local A-frag row (and +8)

    const float* qp = g_q + (size_t)bh * NPOS * DH;
    const float* kp = g_k + (size_t)bh * NPOS * DH;
    const float* vp = g_v + (size_t)bh * NPOS * DH;

    {   // load Q tile [token][d] -> Qs, float4 coalesced
        int r0 = tid >> 5; int c4 = (tid & 31) * 4;
#pragma unroll
        for (int p=0;p<16;p++) {
            int r = r0 + p*4;
            float4 v = make_float4(0.f,0.f,0.f,0.f);
            if (qbase + r < NPOS) v = *(const float4*)&qp[(size_t)(qbase + r)*DH + c4];
            *(float4*)&Qs[r*132 + c4] = v;
        }
    }

    float m0=-1e30f, m1=-1e30f, l0=0.f, l1=0.f;
    float O[16][4];
#pragma unroll
    for (int nb=0;nb<16;nb++)
#pragma unroll
        for (int c=0;c<4;c++) O[nb][c] = 0.f;

    for (int ktile = 0; ktile < 25; ktile++) {
        const int kb = ktile * 64;
        __syncthreads();   // prior PV readers of Ks(Ps)/Vs done
        {   // load K & V tiles
            int r0 = tid >> 5; int c4 = (tid & 31) * 4;
#pragma unroll
            for (int p=0;p<16;p++) {
                int r = r0 + p*4;
                bool ok = (kb + r) < NPOS;
                float4 kv = make_float4(0.f,0.f,0.f,0.f);
                float4 vv = make_float4(0.f,0.f,0.f,0.f);
                if (ok) {
                    kv = *(const float4*)&kp[(size_t)(kb + r)*DH + c4];
                    vv = *(const float4*)&vp[(size_t)(kb + r)*DH + c4];
                }
                *(float4*)&Ks[r*132 + c4] = kv;
                *(float4*)&Vs[r*132 + c4] = vv;
            }
        }
        __syncthreads();

        // ---- S = Q K'^T : per warp m16 x n64, k=128 ----
        float S[8][4];
#pragma unroll
        for (int nb=0;nb<8;nb++)
#pragma unroll
            for (int c=0;c<4;c++) S[nb][c] = 0.f;

#pragma unroll
        for (int kc = 0; kc < 16; kc++) {
            int k0 = kc*8;
            uint32_t a0 = __float_as_uint(Qs[ row0    *132 + k0 + tig    ]);
            uint32_t a1 = __float_as_uint(Qs[(row0+8) *132 + k0 + tig    ]);
            uint32_t a2 = __float_as_uint(Qs[ row0    *132 + k0 + tig + 4]);
            uint32_t a3 = __float_as_uint(Qs[(row0+8) *132 + k0 + tig + 4]);
#pragma unroll
            for (int nb = 0; nb < 8; nb++) {
                uint32_t b0 = __float_as_uint(Ks[(nb*8 + gid)*132 + k0 + tig    ]);
                uint32_t b1 = __float_as_uint(Ks[(nb*8 + gid)*132 + k0 + tig + 4]);
                mma_tf32(S[nb], a0,a1,a2,a3, b0,b1);
            }
        }

        if (kb + 64 > NPOS) {   // mask tail key columns
#pragma unroll
            for (int nb=0;nb<8;nb++) {
                int c0 = kb + nb*8 + 2*tig;
                if (c0     >= NPOS) { S[nb][0] = -1e30f; S[nb][2] = -1e30f; }
                if (c0 + 1 >= NPOS) { S[nb][1] = -1e30f; S[nb][3] = -1e30f; }
            }
        }

        // ---- online softmax (rows row0 / row0+8; reduce over 4-lane group) ----
        float mx0 = -1e30f, mx1 = -1e30f;
#pragma unroll
        for (int nb=0;nb<8;nb++) {
            mx0 = fmaxf(mx0, fmaxf(S[nb][0], S[nb][1]));
            mx1 = fmaxf(mx1, fmaxf(S[nb][2], S[nb][3]));
        }
        mx0 = fmaxf(mx0, __shfl_xor_sync(0xffffffffu, mx0, 1));
        mx0 = fmaxf(mx0, __shfl_xor_sync(0xffffffffu, mx0, 2));
        mx1 = fmaxf(mx1, __shfl_xor_sync(0xffffffffu, mx1, 1));
        mx1 = fmaxf(mx1, __shfl_xor_sync(0xffffffffu, mx1, 2));
        float mn0 = fmaxf(m0, mx0), mn1 = fmaxf(m1, mx1);
        float corr0 = __expf(m0 - mn0), corr1 = __expf(m1 - mn1);
        m0 = mn0; m1 = mn1;
        float rs0 = 0.f, rs1 = 0.f;
#pragma unroll
        for (int nb=0;nb<8;nb++) {
            S[nb][0] = __expf(S[nb][0] - m0); rs0 += S[nb][0];
            S[nb][1] = __expf(S[nb][1] - m0); rs0 += S[nb][1];
            S[nb][2] = __expf(S[nb][2] - m1); rs1 += S[nb][2];
            S[nb][3] = __expf(S[nb][3] - m1); rs1 += S[nb][3];
        }
        rs0 += __shfl_xor_sync(0xffffffffu, rs0, 1);
        rs0 += __shfl_xor_sync(0xffffffffu, rs0, 2);
        rs1 += __shfl_xor_sync(0xffffffffu, rs1, 1);
        rs1 += __shfl_xor_sync(0xffffffffu, rs1, 2);
        l0 = l0*corr0 + rs0;
        l1 = l1*corr1 + rs1;
#pragma unroll
        for (int nb=0;nb<16;nb++) {
            O[nb][0] *= corr0; O[nb][1] *= corr0;
            O[nb][2] *= corr1; O[nb][3] *= corr1;
        }

        __syncthreads();   // all warps done reading Ks -> safe to overlay Ps
#pragma unroll
        for (int nb=0;nb<8;nb++) {
            float2 p01 = make_float2(to_tf32(S[nb][0]), to_tf32(S[nb][1]));
            float2 p23 = make_float2(to_tf32(S[nb][2]), to_tf32(S[nb][3]));
            *(float2*)&Ps[ row0    *68 + nb*8 + 2*tig] = p01;
            *(float2*)&Ps[(row0+8) *68 + nb*8 + 2*tig] = p23;
        }
        __syncwarp();      // warp-local STS->LDS ordering (each warp reads own P rows)

        // ---- O += P V : per warp m16 x n128, k=64 ----
#pragma unroll
        for (int kc = 0; kc < 8; kc++) {
            int j0 = kc*8;
            uint32_t a0 = __float_as_uint(Ps[ row0    *68 + j0 + tig    ]);
            uint32_t a1 = __float_as_uint(Ps[(row0+8) *68 + j0 + tig    ]);
            uint32_t a2 = __float_as_uint(Ps[ row0    *68 + j0 + tig + 4]);
            uint32_t a3 = __float_as_uint(Ps[(row0+8) *68 + j0 + tig + 4]);
#pragma unroll
            for (int nb = 0; nb < 16; nb++) {
                uint32_t b0 = __float_as_uint(Vs[(j0 + tig    )*132 + nb*8 + gid]);
                uint32_t b1 = __float_as_uint(Vs[(j0 + tig + 4)*132 + nb*8 + gid]);
                mma_tf32(O[nb], a0,a1,a2,a3, b0,b1);
            }
        }
    }

    // ---- finalize, transpose through smem, coalesced store ----
    float inv0 = 1.0f / l0, inv1 = 1.0f / l1;
    __syncthreads();       // all PV reads of Ks/Vs done before Od overlay
#pragma unroll
    for (int nb=0;nb<16;nb++) {
        Od[(nb*8 + 2*tig    )*68 + row0    ] = O[nb][0] * inv0;
        Od[(nb*8 + 2*tig + 1)*68 + row0    ] = O[nb][1] * inv0;
        Od[(nb*8 + 2*tig    )*68 + row0 + 8] = O[nb][2] * inv1;
        Od[(nb*8 + 2*tig + 1)*68 + row0 + 8] = O[nb][3] * inv1;
    }
    __syncthreads();

    const int b = bh >> 2, head = bh & 3;
    const size_t ch0 = (size_t)b*512 + head*128;
    {
        int t2 = (tid & 31) * 2;
#pragma unroll
        for (int p=0;p<32;p++) {
            int dd = (tid >> 5) + p*4;
            if (qbase + t2 < NPOS) {
                float2 v = *(const float2*)&Od[dd*68 + t2];
                *(float2*)&out[(ch0 + dd)*NPOS + qbase + t2] = v;
            }
        }
    }
}

// ---------------------------------------------------------------------------
extern "C" void kernel_launch(void* const* d_in, const int* in_sizes, int n_in,
                              void* d_out, int out_size)
{
    const float* fmap = (const float*)d_in[0];
    const float* Wq   = (const float*)d_in[1];
    const float* pf   = (const float*)d_in[2];
    const float* ph   = (const float*)d_in[3];
    const float* pw   = (const float*)d_in[4];
    float* out = (float*)d_out;

    dim3 gA(25, 24, BATCH);
    qkv_kernel<<<gA, 256>>>(fmap, Wq, pf, ph, pw);

    const size_t smemB = (size_t)25344 * sizeof(float);   // 99 KB
    cudaFuncSetAttribute(attn_kernel, cudaFuncAttributeMaxDynamicSharedMemorySize,
                         (int)smemB);
    dim3 gB(25, 32);
    attn_kernel<<<gB, 128, smemB>>>(out);
}

// round 4
// speedup vs baseline: 2.0725x; 1.1358x over previous
#include <cuda_runtime.h>
#include <math.h>
#include <stdint.h>

#define BATCH 8
#define CIN   256
#define NPOS  1568
#define NH    4
#define DH    128

__device__ float g_q[BATCH*NH*NPOS*DH];   // [bh][tok][d], tf32-rounded, pre-scaled
__device__ float g_k[BATCH*NH*NPOS*DH];   // + positional emb folded
__device__ float g_v[BATCH*NH*NPOS*DH];

__device__ __forceinline__ float to_tf32(float x) {
    uint32_t u;
    asm("cvt.rna.tf32.f32 %0, %1;" : "=r"(u) : "f"(x));
    return __uint_as_float(u);
}
__device__ __forceinline__ void mma_tf32(float c[4],
        uint32_t a0, uint32_t a1, uint32_t a2, uint32_t a3,
        uint32_t b0, uint32_t b1) {
    asm volatile(
        "mma.sync.aligned.m16n8k8.row.col.f32.tf32.tf32.f32 "
        "{%0,%1,%2,%3}, {%4,%5,%6,%7}, {%8,%9}, {%0,%1,%2,%3};\n"
        : "+f"(c[0]), "+f"(c[1]), "+f"(c[2]), "+f"(c[3])
        : "r"(a0), "r"(a1), "r"(a2), "r"(a3), "r"(b0), "r"(b1));
}
__device__ __forceinline__ void cp16(uint32_t dst, const void* src, bool ok) {
    unsigned sz = ok ? 16u : 0u;
    asm volatile("cp.async.cg.shared.global [%0], [%1], 16, %2;\n"
                 :: "r"(dst), "l"(src), "r"(sz));
}
#define CP_COMMIT()  asm volatile("cp.async.commit_group;\n")
#define CP_WAIT(N)   asm volatile("cp.async.wait_group %0;\n" :: "n"(N))

// ---------------------------------------------------------------------------
// Kernel A: QKV projection GEMM in fp32 FFMA (full precision — tf32 here was
// the round-3 accuracy regression). Epilogue: scale Q, fold emb into K,
// round once to tf32, store [bh][token][d].
// ---------------------------------------------------------------------------
__global__ __launch_bounds__(256) void qkv_kernel(
    const float* __restrict__ fmap, const float* __restrict__ Wq,
    const float* __restrict__ pf, const float* __restrict__ ph,
    const float* __restrict__ pw)
{
    __shared__ float As[16][68];
    __shared__ float Bs[16][64];

    const int tid = threadIdx.x;
    const int tx = tid & 15, ty = tid >> 4;
    const int pbase = blockIdx.x * 64;
    const int obase = blockIdx.y * 64;
    const int b     = blockIdx.z;

    float acc[4][4];
#pragma unroll
    for (int r=0;r<4;r++)
#pragma unroll
        for (int c=0;c<4;c++) acc[r][c] = 0.f;

    for (int k0 = 0; k0 < CIN; k0 += 16) {
        {
            int k_l = tid & 15, o_l = tid >> 4;
#pragma unroll
            for (int p=0;p<4;p++)
                As[k_l][o_l + p*16] = Wq[(obase + o_l + p*16)*CIN + k0 + k_l];
        }
        {
            int pos_l = tid & 63, k_l = tid >> 6;
#pragma unroll
            for (int p=0;p<4;p++) {
                int kk = k_l + p*4;
                int pos = pbase + pos_l;
                Bs[kk][pos_l] = (pos < NPOS) ? fmap[(b*CIN + k0 + kk)*NPOS + pos] : 0.f;
            }
        }
        __syncthreads();
#pragma unroll
        for (int kk=0; kk<16; kk++) {
            float4 av = *(const float4*)&As[kk][ty*4];
            float4 bv = *(const float4*)&Bs[kk][tx*4];
            acc[0][0] += av.x*bv.x; acc[0][1] += av.x*bv.y; acc[0][2] += av.x*bv.z; acc[0][3] += av.x*bv.w;
            acc[1][0] += av.y*bv.x; acc[1][1] += av.y*bv.y; acc[1][2] += av.y*bv.z; acc[1][3] += av.y*bv.w;
            acc[2][0] += av.z*bv.x; acc[2][1] += av.z*bv.y; acc[2][2] += av.z*bv.z; acc[2][3] += av.z*bv.w;
            acc[3][0] += av.w*bv.x; acc[3][1] += av.w*bv.y; acc[3][2] += av.w*bv.z; acc[3][3] += av.w*bv.w;
        }
        __syncthreads();
    }

    const float scl = 0.08838834764831845f;  // 128^-0.5
#pragma unroll
    for (int r=0;r<4;r++) {
        int o    = obase + ty*4 + r;
        int sec  = o >> 9;          // 0=q 1=k 2=v (uniform per 64-row tile)
        int head = (o >> 7) & 3;
        int d    = o & 127;
        int bh   = b*NH + head;
#pragma unroll
        for (int c=0;c<4;c++) {
            int pos = pbase + tx*4 + c;
            if (pos >= NPOS) continue;
            float v = acc[r][c];
            size_t idx = (size_t)(bh*NPOS + pos)*DH + d;
            if (sec == 0) {
                g_q[idx] = to_tf32(v * scl);
            } else if (sec == 1) {
                int f_ = pos / 196; int rem = pos - f_*196;
                int h_ = rem / 14;  int w_  = rem - h_*14;
                g_k[idx] = to_tf32(v + pf[f_*DH + d] + ph[h_*DH + d] + pw[w_*DH + d]);
            } else {
                g_v[idx] = to_tf32(v);
            }
        }
    }
}

// ---------------------------------------------------------------------------
// Kernel B: flash attention, tf32 mma, cp.async double-buffered K + pipelined V.
// 128 threads / 4 warps. Br=64, Bc=64, d=128. Q A-frags persist in registers.
// P passed c-frag -> a-frag via intra-quad shuffles (no smem round trip).
// smem 96KB: K0[8192] K1[8192] V[8192] floats (swizzled). Od epilogue overlays.
// Numerically identical to the round-2 passing version.
// ---------------------------------------------------------------------------
__global__ __launch_bounds__(128, 2) void attn_kernel(float* __restrict__ out)
{
    extern __shared__ float sm[];
    float* Kb[2] = { sm, sm + 8192 };
    float* Vb    = sm + 16384;
    float* Od    = sm;                 // 128 x 68 overlay

    const int tid  = threadIdx.x;
    const int lane = tid & 31, w = tid >> 5;
    const int gid  = lane >> 2, tig = lane & 3;
    const int qt = blockIdx.x, bh = blockIdx.y;
    const int qbase = qt * 64;
    const int row0 = w*16 + gid;
    const int g4 = gid & 4, g3 = gid & 3, tsw = tig << 3, ksw = gid << 2;

    const float* qp = g_q + (size_t)bh * NPOS * DH;
    const float* kp = g_k + (size_t)bh * NPOS * DH;
    const float* vp = g_v + (size_t)bh * NPOS * DH;

    // ---- stage Q through K0 region, hoist A-frags to registers ----
    {
        int r0 = tid >> 5; int c4 = (tid & 31) * 4;
#pragma unroll
        for (int p=0;p<16;p++) {
            int r = r0 + p*4;
            float4 v = make_float4(0.f,0.f,0.f,0.f);
            if (qbase + r < NPOS) v = *(const float4*)&qp[(size_t)(qbase + r)*DH + c4];
            *(float4*)&Kb[0][r*128 + (c4 ^ ((r&7)<<2))] = v;
        }
    }
    __syncthreads();
    uint32_t qa[16][4];
#pragma unroll
    for (int kc=0;kc<16;kc++) {
        int k0 = kc*8;
        qa[kc][0] = __float_as_uint(Kb[0][ row0   *128 + (k0^ksw) + tig]);
        qa[kc][1] = __float_as_uint(Kb[0][(row0+8)*128 + (k0^ksw) + tig]);
        qa[kc][2] = __float_as_uint(Kb[0][ row0   *128 + ((k0+4)^ksw) + tig]);
        qa[kc][3] = __float_as_uint(Kb[0][(row0+8)*128 + ((k0+4)^ksw) + tig]);
    }
    __syncthreads();

    const uint32_t smK0 = (uint32_t)__cvta_generic_to_shared(Kb[0]);
    const uint32_t smK1 = (uint32_t)__cvta_generic_to_shared(Kb[1]);
    const uint32_t smV  = (uint32_t)__cvta_generic_to_shared(Vb);
    const int lr0 = tid >> 5, lc4 = (tid & 31) * 4;

    // prologue prefetch: K(0) then V(0), each its own commit group
#pragma unroll
    for (int p=0;p<16;p++) {
        int r = lr0 + p*4;
        cp16(smK0 + (r*128 + (lc4 ^ ((r&7)<<2)))*4, &kp[(size_t)r*DH + lc4], r < NPOS);
    }
    CP_COMMIT();
#pragma unroll
    for (int p=0;p<16;p++) {
        int r = lr0 + p*4;
        cp16(smV + (r*128 + (lc4 ^ ((r&3)<<3)))*4, &vp[(size_t)r*DH + lc4], r < NPOS);
    }
    CP_COMMIT();

    float m0=-1e30f, m1=-1e30f, l0=0.f, l1=0.f;
    float O[16][4];
#pragma unroll
    for (int nb=0;nb<16;nb++)
#pragma unroll
        for (int c=0;c<4;c++) O[nb][c] = 0.f;

    const int srcA = (lane & ~3) | (tig >> 1);
    const int srcB = srcA + 2;
    const bool odd = (tig & 1);

    for (int t = 0; t < 25; t++) {
        const int kb = t * 64;
        const float* Ks = Kb[t & 1];
        CP_WAIT(1);              // K(t) landed (V(t) may still fly)
        __syncthreads();

        // ---- S = Q K'^T ----
        float S[8][4];
#pragma unroll
        for (int nb=0;nb<8;nb++)
#pragma unroll
            for (int c=0;c<4;c++) S[nb][c] = 0.f;
#pragma unroll
        for (int kc=0;kc<16;kc++) {
            int k0 = kc*8;
#pragma unroll
            for (int nb=0;nb<8;nb++) {
                int r = nb*8 + gid;
                uint32_t b0 = __float_as_uint(Ks[r*128 + (k0^ksw) + tig]);
                uint32_t b1 = __float_as_uint(Ks[r*128 + ((k0+4)^ksw) + tig]);
                mma_tf32(S[nb], qa[kc][0],qa[kc][1],qa[kc][2],qa[kc][3], b0,b1);
            }
        }

        // prefetch K(t+1) into the other buffer
        {
            int tn = (t+1 < 25) ? t+1 : 24;
            const float* kpn = kp + (size_t)tn*64*DH;
            uint32_t dstK = (t & 1) ? smK0 : smK1;
#pragma unroll
            for (int p=0;p<16;p++) {
                int r = lr0 + p*4;
                cp16(dstK + (r*128 + (lc4 ^ ((r&7)<<2)))*4,
                     &kpn[(size_t)r*DH + lc4], tn*64 + r < NPOS);
            }
            CP_COMMIT();
        }

        if (kb + 64 > NPOS) {
#pragma unroll
            for (int nb=0;nb<8;nb++) {
                int c0 = kb + nb*8 + 2*tig;
                if (c0     >= NPOS) { S[nb][0] = -1e30f; S[nb][2] = -1e30f; }
                if (c0 + 1 >= NPOS) { S[nb][1] = -1e30f; S[nb][3] = -1e30f; }
            }
        }

        // ---- online softmax ----
        float mx0 = -1e30f, mx1 = -1e30f;
#pragma unroll
        for (int nb=0;nb<8;nb++) {
            mx0 = fmaxf(mx0, fmaxf(S[nb][0], S[nb][1]));
            mx1 = fmaxf(mx1, fmaxf(S[nb][2], S[nb][3]));
        }
        mx0 = fmaxf(mx0, __shfl_xor_sync(0xffffffffu, mx0, 1));
        mx0 = fmaxf(mx0, __shfl_xor_sync(0xffffffffu, mx0, 2));
        mx1 = fmaxf(mx1, __shfl_xor_sync(0xffffffffu, mx1, 1));
        mx1 = fmaxf(mx1, __shfl_xor_sync(0xffffffffu, mx1, 2));
        float mn0 = fmaxf(m0, mx0), mn1 = fmaxf(m1, mx1);
        float corr0 = __expf(m0 - mn0), corr1 = __expf(m1 - mn1);
        m0 = mn0; m1 = mn1;
        float rs0 = 0.f, rs1 = 0.f;
#pragma unroll
        for (int nb=0;nb<8;nb++) {
            S[nb][0] = __expf(S[nb][0] - m0); rs0 += S[nb][0];
            S[nb][1] = __expf(S[nb][1] - m0); rs0 += S[nb][1];
            S[nb][2] = __expf(S[nb][2] - m1); rs1 += S[nb][2];
            S[nb][3] = __expf(S[nb][3] - m1); rs1 += S[nb][3];
        }
        rs0 += __shfl_xor_sync(0xffffffffu, rs0, 1);
        rs0 += __shfl_xor_sync(0xffffffffu, rs0, 2);
        rs1 += __shfl_xor_sync(0xffffffffu, rs1, 1);
        rs1 += __shfl_xor_sync(0xffffffffu, rs1, 2);
        l0 = l0*corr0 + rs0;
        l1 = l1*corr1 + rs1;
#pragma unroll
        for (int nb=0;nb<16;nb++) {
            O[nb][0] *= corr0; O[nb][1] *= corr0;
            O[nb][2] *= corr1; O[nb][3] *= corr1;
        }

        CP_WAIT(1);              // V(t) landed (K(t+1) may still fly)
        __syncthreads();

        // ---- O += P V, P a-frags via intra-quad shuffles ----
#pragma unroll
        for (int kc=0;kc<8;kc++) {
            float r0v = to_tf32(S[kc][0]), r1v = to_tf32(S[kc][1]);
            float r2v = to_tf32(S[kc][2]), r3v = to_tf32(S[kc][3]);
            float x0, x1;
            x0 = __shfl_sync(0xffffffffu, r0v, srcA);
            x1 = __shfl_sync(0xffffffffu, r1v, srcA);
            uint32_t a0 = __float_as_uint(odd ? x1 : x0);
            x0 = __shfl_sync(0xffffffffu, r2v, srcA);
            x1 = __shfl_sync(0xffffffffu, r3v, srcA);
            uint32_t a1 = __float_as_uint(odd ? x1 : x0);
            x0 = __shfl_sync(0xffffffffu, r0v, srcB);
            x1 = __shfl_sync(0xffffffffu, r1v, srcB);
            uint32_t a2 = __float_as_uint(odd ? x1 : x0);
            x0 = __shfl_sync(0xffffffffu, r2v, srcB);
            x1 = __shfl_sync(0xffffffffu, r3v, srcB);
            uint32_t a3 = __float_as_uint(odd ? x1 : x0);
            int j0 = kc*8;
#pragma unroll
            for (int nb=0;nb<16;nb++) {
                uint32_t b0 = __float_as_uint(Vb[(j0+tig  )*128 + ((nb*8+g4)^tsw) + g3]);
                uint32_t b1 = __float_as_uint(Vb[(j0+tig+4)*128 + ((nb*8+g4)^tsw) + g3]);
                mma_tf32(O[nb], a0,a1,a2,a3, b0,b1);
            }
        }
        __syncthreads();         // all warps done with V(t)

        // prefetch V(t+1)
        {
            int tn = (t+1 < 25) ? t+1 : 24;
            const float* vpn = vp + (size_t)tn*64*DH;
#pragma unroll
            for (int p=0;p<16;p++) {
                int r = lr0 + p*4;
                cp16(smV + (r*128 + (lc4 ^ ((r&3)<<3)))*4,
                     &vpn[(size_t)r*DH + lc4], tn*64 + r < NPOS);
            }
            CP_COMMIT();
        }
    }

    // ---- finalize: transpose through smem, coalesced store ----
    CP_WAIT(0);
    __syncthreads();
    float inv0 = 1.0f / l0, inv1 = 1.0f / l1;
#pragma unroll
    for (int nb=0;nb<16;nb++) {
        Od[(nb*8 + 2*tig    )*68 + row0    ] = O[nb][0] * inv0;
        Od[(nb*8 + 2*tig + 1)*68 + row0    ] = O[nb][1] * inv0;
        Od[(nb*8 + 2*tig    )*68 + row0 + 8] = O[nb][2] * inv1;
        Od[(nb*8 + 2*tig + 1)*68 + row0 + 8] = O[nb][3] * inv1;
    }
    __syncthreads();

    const int b = bh >> 2, head = bh & 3;
    const size_t ch0 = (size_t)b*512 + head*128;
    {
        int t2 = (tid & 31) * 2;
#pragma unroll
        for (int p=0;p<32;p++) {
            int dd = (tid >> 5) + p*4;
            if (qbase + t2 < NPOS) {
                float2 v = *(const float2*)&Od[dd*68 + t2];
                *(float2*)&out[(ch0 + dd)*NPOS + qbase + t2] = v;
            }
        }
    }
}

// ---------------------------------------------------------------------------
extern "C" void kernel_launch(void* const* d_in, const int* in_sizes, int n_in,
                              void* d_out, int out_size)
{
    const float* fmap = (const float*)d_in[0];
    const float* Wq   = (const float*)d_in[1];
    const float* pf   = (const float*)d_in[2];
    const float* ph   = (const float*)d_in[3];
    const float* pw   = (const float*)d_in[4];
    float* out = (float*)d_out;

    dim3 gA(25, 24, BATCH);
    qkv_kernel<<<gA, 256>>>(fmap, Wq, pf, ph, pw);

    const size_t smemB = (size_t)24576 * sizeof(float);   // 96 KB
    cudaFuncSetAttribute(attn_kernel, cudaFuncAttributeMaxDynamicSharedMemorySize,
                         (int)smemB);
    dim3 gB(25, 32);
    attn_kernel<<<gB, 128, smemB>>>(out);
}

// round 5
// speedup vs baseline: 2.4809x; 1.1970x over previous
#include <cuda_runtime.h>
#include <math.h>
#include <stdint.h>

#define BATCH 8
#define CIN   256
#define NPOS  1568
#define NH    4
#define DH    128

// Scratch layouts (pi(k) = ((k&3)<<2)|((k>>2)&3) applied within 16-groups):
__device__ float g_q[BATCH*NH*NPOS*DH];   // [bh][tok][pi(d)], pre-scaled, tf32
__device__ float g_k[BATCH*NH*NPOS*DH];   // [bh][tok][pi(d)], emb folded, tf32
__device__ float g_v[BATCH*NH*DH*NPOS];   // [bh][d][pi(tok)], tf32

__device__ __forceinline__ float to_tf32(float x) {
    uint32_t u;
    asm("cvt.rna.tf32.f32 %0, %1;" : "=r"(u) : "f"(x));
    return __uint_as_float(u);
}
__device__ __forceinline__ void mma_tf32(float c[4],
        uint32_t a0, uint32_t a1, uint32_t a2, uint32_t a3,
        uint32_t b0, uint32_t b1) {
    asm volatile(
        "mma.sync.aligned.m16n8k8.row.col.f32.tf32.tf32.f32 "
        "{%0,%1,%2,%3}, {%4,%5,%6,%7}, {%8,%9}, {%0,%1,%2,%3};\n"
        : "+f"(c[0]), "+f"(c[1]), "+f"(c[2]), "+f"(c[3])
        : "r"(a0), "r"(a1), "r"(a2), "r"(a3), "r"(b0), "r"(b1));
}
__device__ __forceinline__ void cp16(uint32_t dst, const void* src, bool ok) {
    unsigned sz = ok ? 16u : 0u;
    asm volatile("cp.async.cg.shared.global [%0], [%1], 16, %2;\n"
                 :: "r"(dst), "l"(src), "r"(sz));
}
#define CP_COMMIT()  asm volatile("cp.async.commit_group;\n")
#define CP_WAIT(N)   asm volatile("cp.async.wait_group %0;\n" :: "n"(N))

// ---------------------------------------------------------------------------
// Kernel A: QKV projection GEMM, fp32 FFMA (accuracy), coalesced epilogue.
// 256 threads, tile 64(o) x 64(pos), BK=16. Epilogue stages the tile through
// smem and writes float4 rows with the pi-permutation folded into the gather.
// ---------------------------------------------------------------------------
__global__ __launch_bounds__(256) void qkv_kernel(
    const float* __restrict__ fmap, const float* __restrict__ Wq,
    const float* __restrict__ pf, const float* __restrict__ ph,
    const float* __restrict__ pw)
{
    __shared__ float SB[4160];        // As(16x68) | Bs(16x64); Ts(64x65) overlay
    float* As = SB;                   // pitch 68
    float* Bs = SB + 1088;            // pitch 64
    float* Ts = SB;                   // pitch 65

    const int tid = threadIdx.x;
    const int tx = tid & 15, ty = tid >> 4;
    const int pbase = blockIdx.x * 64;
    const int obase = blockIdx.y * 64;
    const int b     = blockIdx.z;

    float acc[4][4];
#pragma unroll
    for (int r=0;r<4;r++)
#pragma unroll
        for (int c=0;c<4;c++) acc[r][c] = 0.f;

    for (int k0 = 0; k0 < CIN; k0 += 16) {
        {
            int k_l = tid & 15, o_l = tid >> 4;
#pragma unroll
            for (int p=0;p<4;p++)
                As[k_l*68 + o_l + p*16] = Wq[(obase + o_l + p*16)*CIN + k0 + k_l];
        }
        {
            int pos_l = tid & 63, k_l = tid >> 6;
#pragma unroll
            for (int p=0;p<4;p++) {
                int kk = k_l + p*4;
                int pos = pbase + pos_l;
                Bs[kk*64 + pos_l] = (pos < NPOS) ? fmap[(b*CIN + k0 + kk)*NPOS + pos] : 0.f;
            }
        }
        __syncthreads();
#pragma unroll
        for (int kk=0; kk<16; kk++) {
            float4 av = *(const float4*)&As[kk*68 + ty*4];
            float4 bv = *(const float4*)&Bs[kk*64 + tx*4];
            acc[0][0] += av.x*bv.x; acc[0][1] += av.x*bv.y; acc[0][2] += av.x*bv.z; acc[0][3] += av.x*bv.w;
            acc[1][0] += av.y*bv.x; acc[1][1] += av.y*bv.y; acc[1][2] += av.y*bv.z; acc[1][3] += av.y*bv.w;
            acc[2][0] += av.z*bv.x; acc[2][1] += av.z*bv.y; acc[2][2] += av.z*bv.z; acc[2][3] += av.z*bv.w;
            acc[3][0] += av.w*bv.x; acc[3][1] += av.w*bv.y; acc[3][2] += av.w*bv.z; acc[3][3] += av.w*bv.w;
        }
        __syncthreads();
    }

    const float scl = 0.08838834764831845f;  // 128^-0.5
    const int sec  = obase >> 9;             // 0=q 1=k 2=v (uniform per tile)
    const int head = (obase >> 7) & 3;
    const int d0   = obase & 127;
    const int bh   = b*NH + head;

    // stage: Q/K transposed [pos][o]; V direct [o][pos]
    if (sec < 2) {
#pragma unroll
        for (int r=0;r<4;r++)
#pragma unroll
            for (int c=0;c<4;c++)
                Ts[(tx*4+c)*65 + ty*4+r] = acc[r][c];
    } else {
#pragma unroll
        for (int r=0;r<4;r++)
#pragma unroll
            for (int c=0;c<4;c++)
                Ts[(ty*4+r)*65 + tx*4+c] = acc[r][c];
    }
    __syncthreads();

    const int rr2 = tid >> 4;
    const int c4  = (tid & 15) * 4;
    const int tq  = (c4 >> 2) & 3;
    const int cb  = c4 & ~15;
    const int lc0 = cb + tq, lc1 = cb + 4 + tq, lc2 = cb + 8 + tq, lc3 = cb + 12 + tq;

#pragma unroll
    for (int pass=0; pass<4; pass++) {
        int r = rr2 + pass*16;
        float v0 = Ts[r*65+lc0], v1 = Ts[r*65+lc1];
        float v2 = Ts[r*65+lc2], v3 = Ts[r*65+lc3];
        if (sec == 2) {
            if (pbase + c4 < NPOS) {
                *(float4*)&g_v[((size_t)bh*DH + d0 + r)*NPOS + pbase + c4] =
                    make_float4(to_tf32(v0), to_tf32(v1), to_tf32(v2), to_tf32(v3));
            }
        } else {
            int pos = pbase + r;
            if (pos < NPOS) {
                size_t o_ = ((size_t)bh*NPOS + pos)*DH + d0 + c4;
                if (sec == 0) {
                    *(float4*)&g_q[o_] = make_float4(
                        to_tf32(v0*scl), to_tf32(v1*scl), to_tf32(v2*scl), to_tf32(v3*scl));
                } else {
                    int f_ = pos / 196; int rem = pos - f_*196;
                    int h_ = rem / 14;  int w_  = rem - h_*14;
                    const float* pfr = pf + f_*DH + d0;
                    const float* phr = ph + h_*DH + d0;
                    const float* pwr = pw + w_*DH + d0;
                    *(float4*)&g_k[o_] = make_float4(
                        to_tf32(v0 + pfr[lc0] + phr[lc0] + pwr[lc0]),
                        to_tf32(v1 + pfr[lc1] + phr[lc1] + pwr[lc1]),
                        to_tf32(v2 + pfr[lc2] + phr[lc2] + pwr[lc2]),
                        to_tf32(v3 + pfr[lc3] + phr[lc3] + pwr[lc3]));
                }
            }
        }
    }
}

// ---------------------------------------------------------------------------
// Kernel B: flash attention, tf32 mma, LDS.128 fragment loads (pi layout),
// cp.async double-buffered K + pipelined V. 128 threads / 4 warps.
// ---------------------------------------------------------------------------
__global__ __launch_bounds__(128, 2) void attn_kernel(float* __restrict__ out)
{
    extern __shared__ float sm[];
    float* Kb[2] = { sm, sm + 8192 };
    float* Vb    = sm + 16384;         // [d=128][tok=64]
    float* Od    = sm;                 // 128 x 68 overlay

    const int tid  = threadIdx.x;
    const int lane = tid & 31, w = tid >> 5;
    const int gid  = lane >> 2, tig = lane & 3;
    const int qt = blockIdx.x, bh = blockIdx.y;
    const int qbase = qt * 64;
    const int row0 = w*16 + gid;
    const int gsw = gid << 4;          // K/Q swizzle key
    const int vsw = (gid & 3) << 4;    // V swizzle key

    const float* qp = g_q + (size_t)bh * NPOS * DH;
    const float* kp = g_k + (size_t)bh * NPOS * DH;
    const float* vp = g_v + (size_t)bh * DH * NPOS;

    // ---- stage Q through K0 region, hoist A-frags to registers ----
    {
        int r0 = tid >> 5; int c4 = (tid & 31) * 4;
#pragma unroll
        for (int p=0;p<16;p++) {
            int r = r0 + p*4;
            float4 v = make_float4(0.f,0.f,0.f,0.f);
            if (qbase + r < NPOS) v = *(const float4*)&qp[(size_t)(qbase + r)*DH + c4];
            *(float4*)&Kb[0][r*128 + (c4 ^ ((r&7)<<4))] = v;
        }
    }
    __syncthreads();
    uint32_t qa[16][4];
#pragma unroll
    for (int kpi=0;kpi<8;kpi++) {
        float4 r0 = *(const float4*)&Kb[0][ row0   *128 + ((kpi*16) ^ gsw) + tig*4];
        float4 r1 = *(const float4*)&Kb[0][(row0+8)*128 + ((kpi*16) ^ gsw) + tig*4];
        qa[2*kpi  ][0] = __float_as_uint(r0.x); qa[2*kpi  ][1] = __float_as_uint(r1.x);
        qa[2*kpi  ][2] = __float_as_uint(r0.y); qa[2*kpi  ][3] = __float_as_uint(r1.y);
        qa[2*kpi+1][0] = __float_as_uint(r0.z); qa[2*kpi+1][1] = __float_as_uint(r1.z);
        qa[2*kpi+1][2] = __float_as_uint(r0.w); qa[2*kpi+1][3] = __float_as_uint(r1.w);
    }
    __syncthreads();

    const uint32_t smK0 = (uint32_t)__cvta_generic_to_shared(Kb[0]);
    const uint32_t smK1 = (uint32_t)__cvta_generic_to_shared(Kb[1]);
    const uint32_t smV  = (uint32_t)__cvta_generic_to_shared(Vb);
    const int lr0 = tid >> 5, lc4 = (tid & 31) * 4;       // K producer (row=tok)
    const int vr0 = tid >> 4, vc4 = (tid & 15) * 4;       // V producer (row=d)

    // prologue prefetch: K(0) then V(0)
#pragma unroll
    for (int p=0;p<16;p++) {
        int r = lr0 + p*4;
        cp16(smK0 + (r*128 + (lc4 ^ ((r&7)<<4)))*4, &kp[(size_t)r*DH + lc4], r < NPOS);
    }
    CP_COMMIT();
#pragma unroll
    for (int p=0;p<16;p++) {
        int r = vr0 + p*8;
        cp16(smV + (r*64 + (vc4 ^ ((r&3)<<4)))*4, &vp[(size_t)r*NPOS + vc4], vc4 < NPOS);
    }
    CP_COMMIT();

    float m0=-1e30f, m1=-1e30f, l0=0.f, l1=0.f;
    float O[16][4];
#pragma unroll
    for (int nb=0;nb<16;nb++)
#pragma unroll
        for (int c=0;c<4;c++) O[nb][c] = 0.f;

    const int srcA = (lane & ~3) | (tig >> 1);
    const int srcB = srcA + 2;
    const bool odd = (tig & 1);

    for (int t = 0; t < 25; t++) {
        const int kb = t * 64;
        const float* Ks = Kb[t & 1];
        CP_WAIT(1);              // K(t) landed
        __syncthreads();

        // ---- S = Q K'^T : one LDS.128 feeds two mma ----
        float S[8][4];
#pragma unroll
        for (int nb=0;nb<8;nb++)
#pragma unroll
            for (int c=0;c<4;c++) S[nb][c] = 0.f;
#pragma unroll
        for (int kpi=0;kpi<8;kpi++) {
#pragma unroll
            for (int nb=0;nb<8;nb++) {
                int rr = nb*8 + gid;
                float4 kv = *(const float4*)&Ks[rr*128 + ((kpi*16) ^ gsw) + tig*4];
                mma_tf32(S[nb], qa[2*kpi  ][0],qa[2*kpi  ][1],qa[2*kpi  ][2],qa[2*kpi  ][3],
                         __float_as_uint(kv.x), __float_as_uint(kv.y));
                mma_tf32(S[nb], qa[2*kpi+1][0],qa[2*kpi+1][1],qa[2*kpi+1][2],qa[2*kpi+1][3],
                         __float_as_uint(kv.z), __float_as_uint(kv.w));
            }
        }

        // prefetch K(t+1)
        {
            int tn = (t+1 < 25) ? t+1 : 24;
            const float* kpn = kp + (size_t)tn*64*DH;
            uint32_t dstK = (t & 1) ? smK0 : smK1;
#pragma unroll
            for (int p=0;p<16;p++) {
                int r = lr0 + p*4;
                cp16(dstK + (r*128 + (lc4 ^ ((r&7)<<4)))*4,
                     &kpn[(size_t)r*DH + lc4], tn*64 + r < NPOS);
            }
            CP_COMMIT();
        }

        if (kb + 64 > NPOS) {
#pragma unroll
            for (int nb=0;nb<8;nb++) {
                int c0 = kb + nb*8 + 2*tig;
                if (c0     >= NPOS) { S[nb][0] = -1e30f; S[nb][2] = -1e30f; }
                if (c0 + 1 >= NPOS) { S[nb][1] = -1e30f; S[nb][3] = -1e30f; }
            }
        }

        // ---- online softmax ----
        float mx0 = -1e30f, mx1 = -1e30f;
#pragma unroll
        for (int nb=0;nb<8;nb++) {
            mx0 = fmaxf(mx0, fmaxf(S[nb][0], S[nb][1]));
            mx1 = fmaxf(mx1, fmaxf(S[nb][2], S[nb][3]));
        }
        mx0 = fmaxf(mx0, __shfl_xor_sync(0xffffffffu, mx0, 1));
        mx0 = fmaxf(mx0, __shfl_xor_sync(0xffffffffu, mx0, 2));
        mx1 = fmaxf(mx1, __shfl_xor_sync(0xffffffffu, mx1, 1));
        mx1 = fmaxf(mx1, __shfl_xor_sync(0xffffffffu, mx1, 2));
        float mn0 = fmaxf(m0, mx0), mn1 = fmaxf(m1, mx1);
        float corr0 = __expf(m0 - mn0), corr1 = __expf(m1 - mn1);
        m0 = mn0; m1 = mn1;
        float rs0 = 0.f, rs1 = 0.f;
#pragma unroll
        for (int nb=0;nb<8;nb++) {
            S[nb][0] = __expf(S[nb][0] - m0); rs0 += S[nb][0];
            S[nb][1] = __expf(S[nb][1] - m0); rs0 += S[nb][1];
            S[nb][2] = __expf(S[nb][2] - m1); rs1 += S[nb][2];
            S[nb][3] = __expf(S[nb][3] - m1); rs1 += S[nb][3];
        }
        rs0 += __shfl_xor_sync(0xffffffffu, rs0, 1);
        rs0 += __shfl_xor_sync(0xffffffffu, rs0, 2);
        rs1 += __shfl_xor_sync(0xffffffffu, rs1, 1);
        rs1 += __shfl_xor_sync(0xffffffffu, rs1, 2);
        l0 = l0*corr0 + rs0;
        l1 = l1*corr1 + rs1;
#pragma unroll
        for (int nb=0;nb<16;nb++) {
            O[nb][0] *= corr0; O[nb][1] *= corr0;
            O[nb][2] *= corr1; O[nb][3] *= corr1;
        }

        CP_WAIT(1);              // V(t) landed
        __syncthreads();

        // ---- O += P V : shuffle-built P frags, LDS.128 V frags ----
#pragma unroll
        for (int kpi=0;kpi<4;kpi++) {
            uint32_t pa0[4], pa1[4];
#pragma unroll
            for (int half=0;half<2;half++) {
                int kc = 2*kpi + half;
                uint32_t* pa = half ? pa1 : pa0;
                float r0v = to_tf32(S[kc][0]), r1v = to_tf32(S[kc][1]);
                float r2v = to_tf32(S[kc][2]), r3v = to_tf32(S[kc][3]);
                float x0, x1;
                x0 = __shfl_sync(0xffffffffu, r0v, srcA);
                x1 = __shfl_sync(0xffffffffu, r1v, srcA);
                pa[0] = __float_as_uint(odd ? x1 : x0);
                x0 = __shfl_sync(0xffffffffu, r2v, srcA);
                x1 = __shfl_sync(0xffffffffu, r3v, srcA);
                pa[1] = __float_as_uint(odd ? x1 : x0);
                x0 = __shfl_sync(0xffffffffu, r0v, srcB);
                x1 = __shfl_sync(0xffffffffu, r1v, srcB);
                pa[2] = __float_as_uint(odd ? x1 : x0);
                x0 = __shfl_sync(0xffffffffu, r2v, srcB);
                x1 = __shfl_sync(0xffffffffu, r3v, srcB);
                pa[3] = __float_as_uint(odd ? x1 : x0);
            }
#pragma unroll
            for (int nb=0;nb<16;nb++) {
                int rr = nb*8 + gid;
                float4 vv = *(const float4*)&Vb[rr*64 + ((kpi*16) ^ vsw) + tig*4];
                mma_tf32(O[nb], pa0[0],pa0[1],pa0[2],pa0[3],
                         __float_as_uint(vv.x), __float_as_uint(vv.y));
                mma_tf32(O[nb], pa1[0],pa1[1],pa1[2],pa1[3],
                         __float_as_uint(vv.z), __float_as_uint(vv.w));
            }
        }
        __syncthreads();         // all warps done with V(t)

        // prefetch V(t+1)
        {
            int tn = (t+1 < 25) ? t+1 : 24;
            const float* vpn = vp + (size_t)tn*64;
#pragma unroll
            for (int p=0;p<16;p++) {
                int r = vr0 + p*8;
                cp16(smV + (r*64 + (vc4 ^ ((r&3)<<4)))*4,
                     &vpn[(size_t)r*NPOS + vc4], tn*64 + vc4 < NPOS);
            }
            CP_COMMIT();
        }
    }

    // ---- finalize: transpose through smem, coalesced store ----
    CP_WAIT(0);
    __syncthreads();
    float inv0 = 1.0f / l0, inv1 = 1.0f / l1;
#pragma unroll
    for (int nb=0;nb<16;nb++) {
        Od[(nb*8 + 2*tig    )*68 + row0    ] = O[nb][0] * inv0;
        Od[(nb*8 + 2*tig + 1)*68 + row0    ] = O[nb][1] * inv0;
        Od[(nb*8 + 2*tig    )*68 + row0 + 8] = O[nb][2] * inv1;
        Od[(nb*8 + 2*tig + 1)*68 + row0 + 8] = O[nb][3] * inv1;
    }
    __syncthreads();

    const int b = bh >> 2, head = bh & 3;
    const size_t ch0 = (size_t)b*512 + head*128;
    {
        int t2 = (tid & 31) * 2;
#pragma unroll
        for (int p=0;p<32;p++) {
            int dd = (tid >> 5) + p*4;
            if (qbase + t2 < NPOS) {
                float2 v = *(const float2*)&Od[dd*68 + t2];
                *(float2*)&out[(ch0 + dd)*NPOS + qbase + t2] = v;
            }
        }
    }
}

// ---------------------------------------------------------------------------
extern "C" void kernel_launch(void* const* d_in, const int* in_sizes, int n_in,
                              void* d_out, int out_size)
{
    const float* fmap = (const float*)d_in[0];
    const float* Wq   = (const float*)d_in[1];
    const float* pf   = (const float*)d_in[2];
    const float* ph   = (const float*)d_in[3];
    const float* pw   = (const float*)d_in[4];
    float* out = (float*)d_out;

    dim3 gA(25, 24, BATCH);
    qkv_kernel<<<gA, 256>>>(fmap, Wq, pf, ph, pw);

    const size_t smemB = (size_t)24576 * sizeof(float);   // 96 KB
    cudaFuncSetAttribute(attn_kernel, cudaFuncAttributeMaxDynamicSharedMemorySize,
                         (int)smemB);
    dim3 gB(25, 32);
    attn_kernel<<<gB, 128, smemB>>>(out);
}

// round 6
// speedup vs baseline: 2.9204x; 1.1772x over previous
#include <cuda_runtime.h>
#include <math.h>
#include <stdint.h>

#define BATCH 8
#define CIN   256
#define NPOS  1568
#define NH    4
#define DH    128

// Scratch layouts (pi(k) = ((k&3)<<2)|((k>>2)&3) applied within 16-groups):
__device__ float g_q[BATCH*NH*NPOS*DH];   // [bh][tok][pi(d)], pre-scaled, tf32
__device__ float g_k[BATCH*NH*NPOS*DH];   // [bh][tok][pi(d)], emb folded, tf32
__device__ float g_v[BATCH*NH*DH*NPOS];   // [bh][d][pi(tok)], tf32

__device__ __forceinline__ float to_tf32(float x) {
    uint32_t u;
    asm("cvt.rna.tf32.f32 %0, %1;" : "=r"(u) : "f"(x));
    return __uint_as_float(u);
}
__device__ __forceinline__ void mma_tf32(float c[4],
        uint32_t a0, uint32_t a1, uint32_t a2, uint32_t a3,
        uint32_t b0, uint32_t b1) {
    asm volatile(
        "mma.sync.aligned.m16n8k8.row.col.f32.tf32.tf32.f32 "
        "{%0,%1,%2,%3}, {%4,%5,%6,%7}, {%8,%9}, {%0,%1,%2,%3};\n"
        : "+f"(c[0]), "+f"(c[1]), "+f"(c[2]), "+f"(c[3])
        : "r"(a0), "r"(a1), "r"(a2), "r"(a3), "r"(b0), "r"(b1));
}
__device__ __forceinline__ void cp16(uint32_t dst, const void* src, bool ok) {
    unsigned sz = ok ? 16u : 0u;
    asm volatile("cp.async.cg.shared.global [%0], [%1], 16, %2;\n"
                 :: "r"(dst), "l"(src), "r"(sz));
}
#define CP_COMMIT()  asm volatile("cp.async.commit_group;\n")
#define CP_WAIT(N)   asm volatile("cp.async.wait_group %0;\n" :: "n"(N))

// ---------------------------------------------------------------------------
// Kernel A: QKV projection via 3xTF32 error-compensated tensor-core GEMM.
// 128 threads / 4 warps, tile 64(o) x 64(pos), K in 4 chunks of 64.
// Each operand split hi/lo; acc += hi*lo + lo*hi + hi*hi  (error ~2^-21).
// Epilogue: stage through smem, coalesced float4 writes with pi folded in.
// ---------------------------------------------------------------------------
__global__ __launch_bounds__(128) void qkv_kernel(
    const float* __restrict__ fmap, const float* __restrict__ Wq,
    const float* __restrict__ pf, const float* __restrict__ ph,
    const float* __restrict__ pw)
{
    extern __shared__ float qsm[];
    float* Ah = qsm;            // 64x64, swizzle c4 ^ ((r&7)<<2)
    float* Al = qsm + 4096;
    float* Bh = qsm + 8192;     // 64x64, swizzle c4 ^ ((r&3)<<3)
    float* Bl = qsm + 12288;
    float* Ts = qsm;            // 64x65 epilogue overlay

    const int tid  = threadIdx.x;
    const int lane = tid & 31, w = tid >> 5;
    const int gid  = lane >> 2, tig = lane & 3;
    const int row0 = w*16 + gid;
    const int pbase = blockIdx.x * 64;
    const int obase = blockIdx.y * 64;
    const int b     = blockIdx.z;
    const int g4 = gid & 4, g3 = gid & 3, tsw = tig << 3, ksw = gid << 2;

    float acc[8][4];
#pragma unroll
    for (int nb=0;nb<8;nb++)
#pragma unroll
        for (int c=0;c<4;c++) acc[nb][c] = 0.f;

    for (int ks = 0; ks < 4; ks++) {
        {   // A tile: W[obase+r][ks*64 + c], split hi/lo
            int r0 = tid >> 4, c4 = (tid & 15) * 4;
#pragma unroll
            for (int p=0;p<8;p++) {
                int r = r0 + p*8;
                float4 v = *(const float4*)&Wq[(obase + r)*CIN + ks*64 + c4];
                float hx = to_tf32(v.x), hy = to_tf32(v.y), hz = to_tf32(v.z), hw = to_tf32(v.w);
                int o = r*64 + (c4 ^ ((r&7)<<2));
                *(float4*)&Ah[o] = make_float4(hx, hy, hz, hw);
                *(float4*)&Al[o] = make_float4(to_tf32(v.x-hx), to_tf32(v.y-hy),
                                               to_tf32(v.z-hz), to_tf32(v.w-hw));
            }
        }
        {   // B tile: fmap[b][ks*64 + r][pbase + c], split hi/lo
            int r0 = tid >> 4, c4 = (tid & 15) * 4;
#pragma unroll
            for (int p=0;p<8;p++) {
                int r = r0 + p*8;
                float4 v = make_float4(0.f,0.f,0.f,0.f);
                if (pbase + c4 < NPOS)
                    v = *(const float4*)&fmap[(size_t)(b*CIN + ks*64 + r)*NPOS + pbase + c4];
                float hx = to_tf32(v.x), hy = to_tf32(v.y), hz = to_tf32(v.z), hw = to_tf32(v.w);
                int o = r*64 + (c4 ^ ((r&3)<<3));
                *(float4*)&Bh[o] = make_float4(hx, hy, hz, hw);
                *(float4*)&Bl[o] = make_float4(to_tf32(v.x-hx), to_tf32(v.y-hy),
                                               to_tf32(v.z-hz), to_tf32(v.w-hw));
            }
        }
        __syncthreads();
#pragma unroll
        for (int kc=0; kc<8; kc++) {
            int k0 = kc*8;
            uint32_t ah0 = __float_as_uint(Ah[ row0   *64 + (k0^ksw) + tig]);
            uint32_t ah1 = __float_as_uint(Ah[(row0+8)*64 + (k0^ksw) + tig]);
            uint32_t ah2 = __float_as_uint(Ah[ row0   *64 + ((k0+4)^ksw) + tig]);
            uint32_t ah3 = __float_as_uint(Ah[(row0+8)*64 + ((k0+4)^ksw) + tig]);
            uint32_t al0 = __float_as_uint(Al[ row0   *64 + (k0^ksw) + tig]);
            uint32_t al1 = __float_as_uint(Al[(row0+8)*64 + (k0^ksw) + tig]);
            uint32_t al2 = __float_as_uint(Al[ row0   *64 + ((k0+4)^ksw) + tig]);
            uint32_t al3 = __float_as_uint(Al[(row0+8)*64 + ((k0+4)^ksw) + tig]);
#pragma unroll
            for (int nb=0; nb<8; nb++) {
                int cA = ((nb*8+g4)^tsw) + g3;
                uint32_t bh0 = __float_as_uint(Bh[(k0+tig  )*64 + cA]);
                uint32_t bh1 = __float_as_uint(Bh[(k0+tig+4)*64 + cA]);
                uint32_t bl0 = __float_as_uint(Bl[(k0+tig  )*64 + cA]);
                uint32_t bl1 = __float_as_uint(Bl[(k0+tig+4)*64 + cA]);
                mma_tf32(acc[nb], ah0,ah1,ah2,ah3, bl0,bl1);   // hi*lo
                mma_tf32(acc[nb], al0,al1,al2,al3, bh0,bh1);   // lo*hi
                mma_tf32(acc[nb], ah0,ah1,ah2,ah3, bh0,bh1);   // hi*hi
            }
        }
        __syncthreads();
    }

    const float scl = 0.08838834764831845f;  // 128^-0.5
    const int sec  = obase >> 9;             // 0=q 1=k 2=v (uniform per tile)
    const int head = (obase >> 7) & 3;
    const int d0   = obase & 127;
    const int bh   = b*NH + head;

    // stage c-frags: Q/K transposed [pos][o]; V direct [o][pos]
    if (sec < 2) {
#pragma unroll
        for (int nb=0;nb<8;nb++)
#pragma unroll
            for (int half=0;half<2;half++)
#pragma unroll
                for (int e=0;e<2;e++)
                    Ts[(nb*8 + 2*tig + e)*65 + row0 + half*8] = acc[nb][half*2+e];
    } else {
#pragma unroll
        for (int nb=0;nb<8;nb++)
#pragma unroll
            for (int half=0;half<2;half++)
#pragma unroll
                for (int e=0;e<2;e++)
                    Ts[(row0 + half*8)*65 + nb*8 + 2*tig + e] = acc[nb][half*2+e];
    }
    __syncthreads();

    const int rr  = tid >> 4;
    const int c4  = (tid & 15) * 4;
    const int tq  = (c4 >> 2) & 3;
    const int cb  = c4 & ~15;
    const int lc0 = cb + tq, lc1 = cb + 4 + tq, lc2 = cb + 8 + tq, lc3 = cb + 12 + tq;

#pragma unroll
    for (int pass=0; pass<8; pass++) {
        int r = rr + pass*8;
        float v0 = Ts[r*65+lc0], v1 = Ts[r*65+lc1];
        float v2 = Ts[r*65+lc2], v3 = Ts[r*65+lc3];
        if (sec == 2) {
            if (pbase + c4 < NPOS) {
                *(float4*)&g_v[((size_t)bh*DH + d0 + r)*NPOS + pbase + c4] =
                    make_float4(to_tf32(v0), to_tf32(v1), to_tf32(v2), to_tf32(v3));
            }
        } else {
            int pos = pbase + r;
            if (pos < NPOS) {
                size_t o_ = ((size_t)bh*NPOS + pos)*DH + d0 + c4;
                if (sec == 0) {
                    *(float4*)&g_q[o_] = make_float4(
                        to_tf32(v0*scl), to_tf32(v1*scl), to_tf32(v2*scl), to_tf32(v3*scl));
                } else {
                    int f_ = pos / 196; int rem = pos - f_*196;
                    int h_ = rem / 14;  int w_  = rem - h_*14;
                    const float* pfr = pf + f_*DH + d0;
                    const float* phr = ph + h_*DH + d0;
                    const float* pwr = pw + w_*DH + d0;
                    *(float4*)&g_k[o_] = make_float4(
                        to_tf32(v0 + pfr[lc0] + phr[lc0] + pwr[lc0]),
                        to_tf32(v1 + pfr[lc1] + phr[lc1] + pwr[lc1]),
                        to_tf32(v2 + pfr[lc2] + phr[lc2] + pwr[lc2]),
                        to_tf32(v3 + pfr[lc3] + phr[lc3] + pwr[lc3]));
                }
            }
        }
    }
}

// ---------------------------------------------------------------------------
// Kernel B: flash attention, tf32 mma, LDS.128 fragment loads (pi layout),
// cp.async double-buffered K + pipelined V. 128 threads / 4 warps. (unchanged)
// ---------------------------------------------------------------------------
__global__ __launch_bounds__(128, 2) void attn_kernel(float* __restrict__ out)
{
    extern __shared__ float sm[];
    float* Kb[2] = { sm, sm + 8192 };
    float* Vb    = sm + 16384;         // [d=128][tok=64]
    float* Od    = sm;                 // 128 x 68 overlay

    const int tid  = threadIdx.x;
    const int lane = tid & 31, w = tid >> 5;
    const int gid  = lane >> 2, tig = lane & 3;
    const int qt = blockIdx.x, bh = blockIdx.y;
    const int qbase = qt * 64;
    const int row0 = w*16 + gid;
    const int gsw = gid << 4;
    const int vsw = (gid & 3) << 4;

    const float* qp = g_q + (size_t)bh * NPOS * DH;
    const float* kp = g_k + (size_t)bh * NPOS * DH;
    const float* vp = g_v + (size_t)bh * DH * NPOS;

    {
        int r0 = tid >> 5; int c4 = (tid & 31) * 4;
#pragma unroll
        for (int p=0;p<16;p++) {
            int r = r0 + p*4;
            float4 v = make_float4(0.f,0.f,0.f,0.f);
            if (qbase + r < NPOS) v = *(const float4*)&qp[(size_t)(qbase + r)*DH + c4];
            *(float4*)&Kb[0][r*128 + (c4 ^ ((r&7)<<4))] = v;
        }
    }
    __syncthreads();
    uint32_t qa[16][4];
#pragma unroll
    for (int kpi=0;kpi<8;kpi++) {
        float4 r0 = *(const float4*)&Kb[0][ row0   *128 + ((kpi*16) ^ gsw) + tig*4];
        float4 r1 = *(const float4*)&Kb[0][(row0+8)*128 + ((kpi*16) ^ gsw) + tig*4];
        qa[2*kpi  ][0] = __float_as_uint(r0.x); qa[2*kpi  ][1] = __float_as_uint(r1.x);
        qa[2*kpi  ][2] = __float_as_uint(r0.y); qa[2*kpi  ][3] = __float_as_uint(r1.y);
        qa[2*kpi+1][0] = __float_as_uint(r0.z); qa[2*kpi+1][1] = __float_as_uint(r1.z);
        qa[2*kpi+1][2] = __float_as_uint(r0.w); qa[2*kpi+1][3] = __float_as_uint(r1.w);
    }
    __syncthreads();

    const uint32_t smK0 = (uint32_t)__cvta_generic_to_shared(Kb[0]);
    const uint32_t smK1 = (uint32_t)__cvta_generic_to_shared(Kb[1]);
    const uint32_t smV  = (uint32_t)__cvta_generic_to_shared(Vb);
    const int lr0 = tid >> 5, lc4 = (tid & 31) * 4;
    const int vr0 = tid >> 4, vc4 = (tid & 15) * 4;

#pragma unroll
    for (int p=0;p<16;p++) {
        int r = lr0 + p*4;
        cp16(smK0 + (r*128 + (lc4 ^ ((r&7)<<4)))*4, &kp[(size_t)r*DH + lc4], r < NPOS);
    }
    CP_COMMIT();
#pragma unroll
    for (int p=0;p<16;p++) {
        int r = vr0 + p*8;
        cp16(smV + (r*64 + (vc4 ^ ((r&3)<<4)))*4, &vp[(size_t)r*NPOS + vc4], vc4 < NPOS);
    }
    CP_COMMIT();

    float m0=-1e30f, m1=-1e30f, l0=0.f, l1=0.f;
    float O[16][4];
#pragma unroll
    for (int nb=0;nb<16;nb++)
#pragma unroll
        for (int c=0;c<4;c++) O[nb][c] = 0.f;

    const int srcA = (lane & ~3) | (tig >> 1);
    const int srcB = srcA + 2;
    const bool odd = (tig & 1);

    for (int t = 0; t < 25; t++) {
        const int kb = t * 64;
        const float* Ks = Kb[t & 1];
        CP_WAIT(1);
        __syncthreads();

        float S[8][4];
#pragma unroll
        for (int nb=0;nb<8;nb++)
#pragma unroll
            for (int c=0;c<4;c++) S[nb][c] = 0.f;
#pragma unroll
        for (int kpi=0;kpi<8;kpi++) {
#pragma unroll
            for (int nb=0;nb<8;nb++) {
                int rr = nb*8 + gid;
                float4 kv = *(const float4*)&Ks[rr*128 + ((kpi*16) ^ gsw) + tig*4];
                mma_tf32(S[nb], qa[2*kpi  ][0],qa[2*kpi  ][1],qa[2*kpi  ][2],qa[2*kpi  ][3],
                         __float_as_uint(kv.x), __float_as_uint(kv.y));
                mma_tf32(S[nb], qa[2*kpi+1][0],qa[2*kpi+1][1],qa[2*kpi+1][2],qa[2*kpi+1][3],
                         __float_as_uint(kv.z), __float_as_uint(kv.w));
            }
        }

        {
            int tn = (t+1 < 25) ? t+1 : 24;
            const float* kpn = kp + (size_t)tn*64*DH;
            uint32_t dstK = (t & 1) ? smK0 : smK1;
#pragma unroll
            for (int p=0;p<16;p++) {
                int r = lr0 + p*4;
                cp16(dstK + (r*128 + (lc4 ^ ((r&7)<<4)))*4,
                     &kpn[(size_t)r*DH + lc4], tn*64 + r < NPOS);
            }
            CP_COMMIT();
        }

        if (kb + 64 > NPOS) {
#pragma unroll
            for (int nb=0;nb<8;nb++) {
                int c0 = kb + nb*8 + 2*tig;
                if (c0     >= NPOS) { S[nb][0] = -1e30f; S[nb][2] = -1e30f; }
                if (c0 + 1 >= NPOS) { S[nb][1] = -1e30f; S[nb][3] = -1e30f; }
            }
        }

        float mx0 = -1e30f, mx1 = -1e30f;
#pragma unroll
        for (int nb=0;nb<8;nb++) {
            mx0 = fmaxf(mx0, fmaxf(S[nb][0], S[nb][1]));
            mx1 = fmaxf(mx1, fmaxf(S[nb][2], S[nb][3]));
        }
        mx0 = fmaxf(mx0, __shfl_xor_sync(0xffffffffu, mx0, 1));
        mx0 = fmaxf(mx0, __shfl_xor_sync(0xffffffffu, mx0, 2));
        mx1 = fmaxf(mx1, __shfl_xor_sync(0xffffffffu, mx1, 1));
        mx1 = fmaxf(mx1, __shfl_xor_sync(0xffffffffu, mx1, 2));
        float mn0 = fmaxf(m0, mx0), mn1 = fmaxf(m1, mx1);
        float corr0 = __expf(m0 - mn0), corr1 = __expf(m1 - mn1);
        m0 = mn0; m1 = mn1;
        float rs0 = 0.f, rs1 = 0.f;
#pragma unroll
        for (int nb=0;nb<8;nb++) {
            S[nb][0] = __expf(S[nb][0] - m0); rs0 += S[nb][0];
            S[nb][1] = __expf(S[nb][1] - m0); rs0 += S[nb][1];
            S[nb][2] = __expf(S[nb][2] - m1); rs1 += S[nb][2];
            S[nb][3] = __expf(S[nb][3] - m1); rs1 += S[nb][3];
        }
        rs0 += __shfl_xor_sync(0xffffffffu, rs0, 1);
        rs0 += __shfl_xor_sync(0xffffffffu, rs0, 2);
        rs1 += __shfl_xor_sync(0xffffffffu, rs1, 1);
        rs1 += __shfl_xor_sync(0xffffffffu, rs1, 2);
        l0 = l0*corr0 + rs0;
        l1 = l1*corr1 + rs1;
#pragma unroll
        for (int nb=0;nb<16;nb++) {
            O[nb][0] *= corr0; O[nb][1] *= corr0;
            O[nb][2] *= corr1; O[nb][3] *= corr1;
        }

        CP_WAIT(1);
        __syncthreads();

#pragma unroll
        for (int kpi=0;kpi<4;kpi++) {
            uint32_t pa0[4], pa1[4];
#pragma unroll
            for (int half=0;half<2;half++) {
                int kc = 2*kpi + half;
                uint32_t* pa = half ? pa1 : pa0;
                float r0v = to_tf32(S[kc][0]), r1v = to_tf32(S[kc][1]);
                float r2v = to_tf32(S[kc][2]), r3v = to_tf32(S[kc][3]);
                float x0, x1;
                x0 = __shfl_sync(0xffffffffu, r0v, srcA);
                x1 = __shfl_sync(0xffffffffu, r1v, srcA);
                pa[0] = __float_as_uint(odd ? x1 : x0);
                x0 = __shfl_sync(0xffffffffu, r2v, srcA);
                x1 = __shfl_sync(0xffffffffu, r3v, srcA);
                pa[1] = __float_as_uint(odd ? x1 : x0);
                x0 = __shfl_sync(0xffffffffu, r0v, srcB);
                x1 = __shfl_sync(0xffffffffu, r1v, srcB);
                pa[2] = __float_as_uint(odd ? x1 : x0);
                x0 = __shfl_sync(0xffffffffu, r2v, srcB);
                x1 = __shfl_sync(0xffffffffu, r3v, srcB);
                pa[3] = __float_as_uint(odd ? x1 : x0);
            }
#pragma unroll
            for (int nb=0;nb<16;nb++) {
                int rr = nb*8 + gid;
                float4 vv = *(const float4*)&Vb[rr*64 + ((kpi*16) ^ vsw) + tig*4];
                mma_tf32(O[nb], pa0[0],pa0[1],pa0[2],pa0[3],
                         __float_as_uint(vv.x), __float_as_uint(vv.y));
                mma_tf32(O[nb], pa1[0],pa1[1],pa1[2],pa1[3],
                         __float_as_uint(vv.z), __float_as_uint(vv.w));
            }
        }
        __syncthreads();

        {
            int tn = (t+1 < 25) ? t+1 : 24;
            const float* vpn = vp + (size_t)tn*64;
#pragma unroll
            for (int p=0;p<16;p++) {
                int r = vr0 + p*8;
                cp16(smV + (r*64 + (vc4 ^ ((r&3)<<4)))*4,
                     &vpn[(size_t)r*NPOS + vc4], tn*64 + vc4 < NPOS);
            }
            CP_COMMIT();
        }
    }

    CP_WAIT(0);
    __syncthreads();
    float inv0 = 1.0f / l0, inv1 = 1.0f / l1;
#pragma unroll
    for (int nb=0;nb<16;nb++) {
        Od[(nb*8 + 2*tig    )*68 + row0    ] = O[nb][0] * inv0;
        Od[(nb*8 + 2*tig + 1)*68 + row0    ] = O[nb][1] * inv0;
        Od[(nb*8 + 2*tig    )*68 + row0 + 8] = O[nb][2] * inv1;
        Od[(nb*8 + 2*tig + 1)*68 + row0 + 8] = O[nb][3] * inv1;
    }
    __syncthreads();

    const int b = bh >> 2, head = bh & 3;
    const size_t ch0 = (size_t)b*512 + head*128;
    {
        int t2 = (tid & 31) * 2;
#pragma unroll
        for (int p=0;p<32;p++) {
            int dd = (tid >> 5) + p*4;
            if (qbase + t2 < NPOS) {
                float2 v = *(const float2*)&Od[dd*68 + t2];
                *(float2*)&out[(ch0 + dd)*NPOS + qbase + t2] = v;
            }
        }
    }
}

// ---------------------------------------------------------------------------
extern "C" void kernel_launch(void* const* d_in, const int* in_sizes, int n_in,
                              void* d_out, int out_size)
{
    const float* fmap = (const float*)d_in[0];
    const float* Wq   = (const float*)d_in[1];
    const float* pf   = (const float*)d_in[2];
    const float* ph   = (const float*)d_in[3];
    const float* pw   = (const float*)d_in[4];
    float* out = (float*)d_out;

    const size_t smemA = (size_t)16384 * sizeof(float);   // 64 KB
    cudaFuncSetAttribute(qkv_kernel, cudaFuncAttributeMaxDynamicSharedMemorySize,
                         (int)smemA);
    dim3 gA(25, 24, BATCH);
    qkv_kernel<<<gA, 128, smemA>>>(fmap, Wq, pf, ph, pw);

    const size_t smemB = (size_t)24576 * sizeof(float);   // 96 KB
    cudaFuncSetAttribute(attn_kernel, cudaFuncAttributeMaxDynamicSharedMemorySize,
                         (int)smemB);
    dim3 gB(25, 32);
    attn_kernel<<<gB, 128, smemB>>>(out);
}

// round 7
// speedup vs baseline: 2.9979x; 1.0265x over previous
#include <cuda_runtime.h>
#include <math.h>
#include <stdint.h>

#define BATCH 8
#define CIN   256
#define NPOS  1568
#define NH    4
#define DH    128

// Scratch layouts:
//  pi(k) = ((k&3)<<2)|((k>>2)&3)           (d-dim of Q/K, 16-groups)
//  rho(j) = 4*((j>>1)&3) + 2*(j>>3) + (j&1) (tok-dim of V, 16-groups)
__device__ float g_q[BATCH*NH*NPOS*DH];   // [bh][tok][pi(d)], *scl*log2e, tf32
__device__ float g_k[BATCH*NH*NPOS*DH];   // [bh][tok][pi(d)], emb folded, tf32
__device__ float g_v[BATCH*NH*DH*NPOS];   // [bh][d][rho(tok)], tf32

__device__ __forceinline__ float to_tf32(float x) {
    uint32_t u;
    asm("cvt.rna.tf32.f32 %0, %1;" : "=r"(u) : "f"(x));
    return __uint_as_float(u);
}
__device__ __forceinline__ float fast_exp2(float x) {
    float y;
    asm("ex2.approx.f32 %0, %1;" : "=f"(y) : "f"(x));
    return y;
}
__device__ __forceinline__ void mma_tf32(float c[4],
        uint32_t a0, uint32_t a1, uint32_t a2, uint32_t a3,
        uint32_t b0, uint32_t b1) {
    asm volatile(
        "mma.sync.aligned.m16n8k8.row.col.f32.tf32.tf32.f32 "
        "{%0,%1,%2,%3}, {%4,%5,%6,%7}, {%8,%9}, {%0,%1,%2,%3};\n"
        : "+f"(c[0]), "+f"(c[1]), "+f"(c[2]), "+f"(c[3])
        : "r"(a0), "r"(a1), "r"(a2), "r"(a3), "r"(b0), "r"(b1));
}
__device__ __forceinline__ void cp16(uint32_t dst, const void* src, bool ok) {
    unsigned sz = ok ? 16u : 0u;
    asm volatile("cp.async.cg.shared.global [%0], [%1], 16, %2;\n"
                 :: "r"(dst), "l"(src), "r"(sz));
}
#define CP_COMMIT()  asm volatile("cp.async.commit_group;\n")
#define CP_WAIT(N)   asm volatile("cp.async.wait_group %0;\n" :: "n"(N))

// ---------------------------------------------------------------------------
// Kernel A: QKV projection via 3xTF32 compensated mma GEMM, with register
// prefetch across the 4 K-chunks. Epilogue: coalesced float4 stores with
// pi (Q/K d-dim) or rho (V tok-dim) folded into the smem gather.
// ---------------------------------------------------------------------------
__global__ __launch_bounds__(128) void qkv_kernel(
    const float* __restrict__ fmap, const float* __restrict__ Wq,
    const float* __restrict__ pf, const float* __restrict__ ph,
    const float* __restrict__ pw)
{
    extern __shared__ float qsm[];
    float* Ah = qsm;            // 64x64, swizzle c4 ^ ((r&7)<<2)
    float* Al = qsm + 4096;
    float* Bh = qsm + 8192;     // 64x64, swizzle c4 ^ ((r&3)<<3)
    float* Bl = qsm + 12288;
    float* Ts = qsm;            // 64x65 epilogue overlay

    const int tid  = threadIdx.x;
    const int lane = tid & 31, w = tid >> 5;
    const int gid  = lane >> 2, tig = lane & 3;
    const int row0 = w*16 + gid;
    const int pbase = blockIdx.x * 64;
    const int obase = blockIdx.y * 64;
    const int b     = blockIdx.z;
    const int g4 = gid & 4, g3 = gid & 3, tsw = tig << 3, ksw = gid << 2;

    const int r0 = tid >> 4, c4l = (tid & 15) * 4;

    float acc[8][4];
#pragma unroll
    for (int nb=0;nb<8;nb++)
#pragma unroll
        for (int c=0;c<4;c++) acc[nb][c] = 0.f;

    float4 ra[8], rb[8];
    {   // prefetch ks=0
#pragma unroll
        for (int p=0;p<8;p++) {
            int r = r0 + p*8;
            ra[p] = *(const float4*)&Wq[(obase + r)*CIN + c4l];
            rb[p] = make_float4(0.f,0.f,0.f,0.f);
            if (pbase + c4l < NPOS)
                rb[p] = *(const float4*)&fmap[(size_t)(b*CIN + r)*NPOS + pbase + c4l];
        }
    }

    for (int ks = 0; ks < 4; ks++) {
        // split & store current chunk
#pragma unroll
        for (int p=0;p<8;p++) {
            int r = r0 + p*8;
            float4 v = ra[p];
            float hx = to_tf32(v.x), hy = to_tf32(v.y), hz = to_tf32(v.z), hw = to_tf32(v.w);
            int o = r*64 + (c4l ^ ((r&7)<<2));
            *(float4*)&Ah[o] = make_float4(hx, hy, hz, hw);
            *(float4*)&Al[o] = make_float4(to_tf32(v.x-hx), to_tf32(v.y-hy),
                                           to_tf32(v.z-hz), to_tf32(v.w-hw));
        }
#pragma unroll
        for (int p=0;p<8;p++) {
            int r = r0 + p*8;
            float4 v = rb[p];
            float hx = to_tf32(v.x), hy = to_tf32(v.y), hz = to_tf32(v.z), hw = to_tf32(v.w);
            int o = r*64 + (c4l ^ ((r&3)<<3));
            *(float4*)&Bh[o] = make_float4(hx, hy, hz, hw);
            *(float4*)&Bl[o] = make_float4(to_tf32(v.x-hx), to_tf32(v.y-hy),
                                           to_tf32(v.z-hz), to_tf32(v.w-hw));
        }
        __syncthreads();

        if (ks < 3) {   // prefetch next chunk (LDG latency hides behind mma)
            int kn = (ks+1)*64;
#pragma unroll
            for (int p=0;p<8;p++) {
                int r = r0 + p*8;
                ra[p] = *(const float4*)&Wq[(obase + r)*CIN + kn + c4l];
                rb[p] = make_float4(0.f,0.f,0.f,0.f);
                if (pbase + c4l < NPOS)
                    rb[p] = *(const float4*)&fmap[(size_t)(b*CIN + kn + r)*NPOS + pbase + c4l];
            }
        }

#pragma unroll
        for (int kc=0; kc<8; kc++) {
            int k0 = kc*8;
            uint32_t ah0 = __float_as_uint(Ah[ row0   *64 + (k0^ksw) + tig]);
            uint32_t ah1 = __float_as_uint(Ah[(row0+8)*64 + (k0^ksw) + tig]);
            uint32_t ah2 = __float_as_uint(Ah[ row0   *64 + ((k0+4)^ksw) + tig]);
            uint32_t ah3 = __float_as_uint(Ah[(row0+8)*64 + ((k0+4)^ksw) + tig]);
            uint32_t al0 = __float_as_uint(Al[ row0   *64 + (k0^ksw) + tig]);
            uint32_t al1 = __float_as_uint(Al[(row0+8)*64 + (k0^ksw) + tig]);
            uint32_t al2 = __float_as_uint(Al[ row0   *64 + ((k0+4)^ksw) + tig]);
            uint32_t al3 = __float_as_uint(Al[(row0+8)*64 + ((k0+4)^ksw) + tig]);
#pragma unroll
            for (int nb=0; nb<8; nb++) {
                int cA = ((nb*8+g4)^tsw) + g3;
                uint32_t bh0 = __float_as_uint(Bh[(k0+tig  )*64 + cA]);
                uint32_t bh1 = __float_as_uint(Bh[(k0+tig+4)*64 + cA]);
                uint32_t bl0 = __float_as_uint(Bl[(k0+tig  )*64 + cA]);
                uint32_t bl1 = __float_as_uint(Bl[(k0+tig+4)*64 + cA]);
                mma_tf32(acc[nb], ah0,ah1,ah2,ah3, bl0,bl1);   // hi*lo
                mma_tf32(acc[nb], al0,al1,al2,al3, bh0,bh1);   // lo*hi
                mma_tf32(acc[nb], ah0,ah1,ah2,ah3, bh0,bh1);   // hi*hi
            }
        }
        __syncthreads();
    }

    // scl * log2(e): attention runs in the exp2 domain
    const float scl = 0.08838834764831845f * 1.4426950408889634f;
    const int sec  = obase >> 9;             // 0=q 1=k 2=v (uniform per tile)
    const int head = (obase >> 7) & 3;
    const int d0   = obase & 127;
    const int bh   = b*NH + head;

    // stage c-frags: Q/K transposed [pos][o]; V direct [o][pos]
    if (sec < 2) {
#pragma unroll
        for (int nb=0;nb<8;nb++)
#pragma unroll
            for (int half=0;half<2;half++)
#pragma unroll
                for (int e=0;e<2;e++)
                    Ts[(nb*8 + 2*tig + e)*65 + row0 + half*8] = acc[nb][half*2+e];
    } else {
#pragma unroll
        for (int nb=0;nb<8;nb++)
#pragma unroll
            for (int half=0;half<2;half++)
#pragma unroll
                for (int e=0;e<2;e++)
                    Ts[(row0 + half*8)*65 + nb*8 + 2*tig + e] = acc[nb][half*2+e];
    }
    __syncthreads();

    const int rr  = tid >> 4;
    const int c4  = (tid & 15) * 4;
    const int tq  = (c4 >> 2) & 3;
    const int cb  = c4 & ~15;
    // pi gather (Q/K d-dim)
    const int lc0 = cb + tq, lc1 = cb + 4 + tq, lc2 = cb + 8 + tq, lc3 = cb + 12 + tq;
    // rho gather (V tok-dim): position 4t+q holds j16 = 2t + 8*(q>>1) + (q&1)
    const int lv0 = cb + 2*tq, lv1 = cb + 2*tq + 1, lv2 = cb + 2*tq + 8, lv3 = cb + 2*tq + 9;

#pragma unroll
    for (int pass=0; pass<8; pass++) {
        int r = rr + pass*8;
        if (sec == 2) {
            if (pbase + c4 < NPOS) {
                float v0 = Ts[r*65+lv0], v1 = Ts[r*65+lv1];
                float v2 = Ts[r*65+lv2], v3 = Ts[r*65+lv3];
                *(float4*)&g_v[((size_t)bh*DH + d0 + r)*NPOS + pbase + c4] =
                    make_float4(to_tf32(v0), to_tf32(v1), to_tf32(v2), to_tf32(v3));
            }
        } else {
            float v0 = Ts[r*65+lc0], v1 = Ts[r*65+lc1];
            float v2 = Ts[r*65+lc2], v3 = Ts[r*65+lc3];
            int pos = pbase + r;
            if (pos < NPOS) {
                size_t o_ = ((size_t)bh*NPOS + pos)*DH + d0 + c4;
                if (sec == 0) {
                    *(float4*)&g_q[o_] = make_float4(
                        to_tf32(v0*scl), to_tf32(v1*scl), to_tf32(v2*scl), to_tf32(v3*scl));
                } else {
                    int f_ = pos / 196; int rem = pos - f_*196;
                    int h_ = rem / 14;  int w_  = rem - h_*14;
                    const float* pfr = pf + f_*DH + d0;
                    const float* phr = ph + h_*DH + d0;
                    const float* pwr = pw + w_*DH + d0;
                    *(float4*)&g_k[o_] = make_float4(
                        to_tf32(v0 + pfr[lc0] + phr[lc0] + pwr[lc0]),
                        to_tf32(v1 + pfr[lc1] + phr[lc1] + pwr[lc1]),
                        to_tf32(v2 + pfr[lc2] + phr[lc2] + pwr[lc2]),
                        to_tf32(v3 + pfr[lc3] + phr[lc3] + pwr[lc3]));
                }
            }
        }
    }
}

// ---------------------------------------------------------------------------
// Kernel B: flash attention. S c-frags feed PV mma DIRECTLY as A-frags
// (k-permutation sigma folded into V's rho token layout) — no shuffles, no
// P smem. exp2-domain softmax. cp.async double-buffered K + pipelined V.
// ---------------------------------------------------------------------------
__global__ __launch_bounds__(128, 2) void attn_kernel(float* __restrict__ out)
{
    extern __shared__ float sm[];
    float* Kb[2] = { sm, sm + 8192 };
    float* Vb    = sm + 16384;         // [d=128][rho(tok)=64]
    float* Od    = sm;                 // 128 x 68 overlay

    const int tid  = threadIdx.x;
    const int lane = tid & 31, w = tid >> 5;
    const int gid  = lane >> 2, tig = lane & 3;
    const int qt = blockIdx.x, bh = blockIdx.y;
    const int qbase = qt * 64;
    const int row0 = w*16 + gid;
    const int gsw = gid << 4;
    const int vsw = (gid & 3) << 4;

    const float* qp = g_q + (size_t)bh * NPOS * DH;
    const float* kp = g_k + (size_t)bh * NPOS * DH;
    const float* vp = g_v + (size_t)bh * DH * NPOS;

    {
        int r0 = tid >> 5; int c4 = (tid & 31) * 4;
#pragma unroll
        for (int p=0;p<16;p++) {
            int r = r0 + p*4;
            float4 v = make_float4(0.f,0.f,0.f,0.f);
            if (qbase + r < NPOS) v = *(const float4*)&qp[(size_t)(qbase + r)*DH + c4];
            *(float4*)&Kb[0][r*128 + (c4 ^ ((r&7)<<4))] = v;
        }
    }
    __syncthreads();
    uint32_t qa[16][4];
#pragma unroll
    for (int kpi=0;kpi<8;kpi++) {
        float4 r0 = *(const float4*)&Kb[0][ row0   *128 + ((kpi*16) ^ gsw) + tig*4];
        float4 r1 = *(const float4*)&Kb[0][(row0+8)*128 + ((kpi*16) ^ gsw) + tig*4];
        qa[2*kpi  ][0] = __float_as_uint(r0.x); qa[2*kpi  ][1] = __float_as_uint(r1.x);
        qa[2*kpi  ][2] = __float_as_uint(r0.y); qa[2*kpi  ][3] = __float_as_uint(r1.y);
        qa[2*kpi+1][0] = __float_as_uint(r0.z); qa[2*kpi+1][1] = __float_as_uint(r1.z);
        qa[2*kpi+1][2] = __float_as_uint(r0.w); qa[2*kpi+1][3] = __float_as_uint(r1.w);
    }
    __syncthreads();

    const uint32_t smK0 = (uint32_t)__cvta_generic_to_shared(Kb[0]);
    const uint32_t smK1 = (uint32_t)__cvta_generic_to_shared(Kb[1]);
    const uint32_t smV  = (uint32_t)__cvta_generic_to_shared(Vb);
    const int lr0 = tid >> 5, lc4 = (tid & 31) * 4;
    const int vr0 = tid >> 4, vc4 = (tid & 15) * 4;

#pragma unroll
    for (int p=0;p<16;p++) {
        int r = lr0 + p*4;
        cp16(smK0 + (r*128 + (lc4 ^ ((r&7)<<4)))*4, &kp[(size_t)r*DH + lc4], r < NPOS);
    }
    CP_COMMIT();
#pragma unroll
    for (int p=0;p<16;p++) {
        int r = vr0 + p*8;
        cp16(smV + (r*64 + (vc4 ^ ((r&3)<<4)))*4, &vp[(size_t)r*NPOS + vc4], vc4 < NPOS);
    }
    CP_COMMIT();

    float m0=-1e30f, m1=-1e30f, l0=0.f, l1=0.f;
    float O[16][4];
#pragma unroll
    for (int nb=0;nb<16;nb++)
#pragma unroll
        for (int c=0;c<4;c++) O[nb][c] = 0.f;

    for (int t = 0; t < 25; t++) {
        const int kb = t * 64;
        const float* Ks = Kb[t & 1];
        CP_WAIT(1);
        __syncthreads();

        float S[8][4];
#pragma unroll
        for (int nb=0;nb<8;nb++)
#pragma unroll
            for (int c=0;c<4;c++) S[nb][c] = 0.f;
#pragma unroll
        for (int kpi=0;kpi<8;kpi++) {
#pragma unroll
            for (int nb=0;nb<8;nb++) {
                int rr = nb*8 + gid;
                float4 kv = *(const float4*)&Ks[rr*128 + ((kpi*16) ^ gsw) + tig*4];
                mma_tf32(S[nb], qa[2*kpi  ][0],qa[2*kpi  ][1],qa[2*kpi  ][2],qa[2*kpi  ][3],
                         __float_as_uint(kv.x), __float_as_uint(kv.y));
                mma_tf32(S[nb], qa[2*kpi+1][0],qa[2*kpi+1][1],qa[2*kpi+1][2],qa[2*kpi+1][3],
                         __float_as_uint(kv.z), __float_as_uint(kv.w));
            }
        }

        {
            int tn = (t+1 < 25) ? t+1 : 24;
            const float* kpn = kp + (size_t)tn*64*DH;
            uint32_t dstK = (t & 1) ? smK0 : smK1;
#pragma unroll
            for (int p=0;p<16;p++) {
                int r = lr0 + p*4;
                cp16(dstK + (r*128 + (lc4 ^ ((r&7)<<4)))*4,
                     &kpn[(size_t)r*DH + lc4], tn*64 + r < NPOS);
            }
            CP_COMMIT();
        }

        if (kb + 64 > NPOS) {
#pragma unroll
            for (int nb=0;nb<8;nb++) {
                int c0 = kb + nb*8 + 2*tig;
                if (c0     >= NPOS) { S[nb][0] = -1e30f; S[nb][2] = -1e30f; }
                if (c0 + 1 >= NPOS) { S[nb][1] = -1e30f; S[nb][3] = -1e30f; }
            }
        }

        // ---- online softmax (log2 domain: S already scaled by log2e) ----
        float mx0 = -1e30f, mx1 = -1e30f;
#pragma unroll
        for (int nb=0;nb<8;nb++) {
            mx0 = fmaxf(mx0, fmaxf(S[nb][0], S[nb][1]));
            mx1 = fmaxf(mx1, fmaxf(S[nb][2], S[nb][3]));
        }
        mx0 = fmaxf(mx0, __shfl_xor_sync(0xffffffffu, mx0, 1));
        mx0 = fmaxf(mx0, __shfl_xor_sync(0xffffffffu, mx0, 2));
        mx1 = fmaxf(mx1, __shfl_xor_sync(0xffffffffu, mx1, 1));
        mx1 = fmaxf(mx1, __shfl_xor_sync(0xffffffffu, mx1, 2));
        float mn0 = fmaxf(m0, mx0), mn1 = fmaxf(m1, mx1);
        float corr0 = fast_exp2(m0 - mn0), corr1 = fast_exp2(m1 - mn1);
        m0 = mn0; m1 = mn1;
        float rs0 = 0.f, rs1 = 0.f;
#pragma unroll
        for (int nb=0;nb<8;nb++) {
            S[nb][0] = fast_exp2(S[nb][0] - m0); rs0 += S[nb][0];
            S[nb][1] = fast_exp2(S[nb][1] - m0); rs0 += S[nb][1];
            S[nb][2] = fast_exp2(S[nb][2] - m1); rs1 += S[nb][2];
            S[nb][3] = fast_exp2(S[nb][3] - m1); rs1 += S[nb][3];
        }
        rs0 += __shfl_xor_sync(0xffffffffu, rs0, 1);
        rs0 += __shfl_xor_sync(0xffffffffu, rs0, 2);
        rs1 += __shfl_xor_sync(0xffffffffu, rs1, 1);
        rs1 += __shfl_xor_sync(0xffffffffu, rs1, 2);
        l0 = l0*corr0 + rs0;
        l1 = l1*corr1 + rs1;
        // skip the O rescale when nothing changed (corr==1 for whole warp)
        unsigned vote = __ballot_sync(0xffffffffu,
                                      (corr0 == 1.f) && (corr1 == 1.f));
        if (vote != 0xffffffffu) {
#pragma unroll
            for (int nb=0;nb<16;nb++) {
                O[nb][0] *= corr0; O[nb][1] *= corr0;
                O[nb][2] *= corr1; O[nb][3] *= corr1;
            }
        }

        CP_WAIT(1);
        __syncthreads();

        // ---- O += P V : S c-frags ARE the A-frags (sigma/rho layout) ----
#pragma unroll
        for (int kpi=0;kpi<4;kpi++) {
            int e = 2*kpi, o = 2*kpi+1;
            uint32_t ea0 = __float_as_uint(to_tf32(S[e][0]));
            uint32_t ea1 = __float_as_uint(to_tf32(S[e][2]));
            uint32_t ea2 = __float_as_uint(to_tf32(S[e][1]));
            uint32_t ea3 = __float_as_uint(to_tf32(S[e][3]));
            uint32_t oa0 = __float_as_uint(to_tf32(S[o][0]));
            uint32_t oa1 = __float_as_uint(to_tf32(S[o][2]));
            uint32_t oa2 = __float_as_uint(to_tf32(S[o][1]));
            uint32_t oa3 = __float_as_uint(to_tf32(S[o][3]));
#pragma unroll
            for (int nb=0;nb<16;nb++) {
                int rr = nb*8 + gid;
                float4 vv = *(const float4*)&Vb[rr*64 + ((kpi*16) ^ vsw) + tig*4];
                mma_tf32(O[nb], ea0,ea1,ea2,ea3,
                         __float_as_uint(vv.x), __float_as_uint(vv.y));
                mma_tf32(O[nb], oa0,oa1,oa2,oa3,
                         __float_as_uint(vv.z), __float_as_uint(vv.w));
            }
        }
        __syncthreads();

        {
            int tn = (t+1 < 25) ? t+1 : 24;
            const float* vpn = vp + (size_t)tn*64;
#pragma unroll
            for (int p=0;p<16;p++) {
                int r = vr0 + p*8;
                cp16(smV + (r*64 + (vc4 ^ ((r&3)<<4)))*4,
                     &vpn[(size_t)r*NPOS + vc4], tn*64 + vc4 < NPOS);
            }
            CP_COMMIT();
        }
    }

    CP_WAIT(0);
    __syncthreads();
    float inv0 = 1.0f / l0, inv1 = 1.0f / l1;
#pragma unroll
    for (int nb=0;nb<16;nb++) {
        Od[(nb*8 + 2*tig    )*68 + row0    ] = O[nb][0] * inv0;
        Od[(nb*8 + 2*tig + 1)*68 + row0    ] = O[nb][1] * inv0;
        Od[(nb*8 + 2*tig    )*68 + row0 + 8] = O[nb][2] * inv1;
        Od[(nb*8 + 2*tig + 1)*68 + row0 + 8] = O[nb][3] * inv1;
    }
    __syncthreads();

    const int b = bh >> 2, head = bh & 3;
    const size_t ch0 = (size_t)b*512 + head*128;
    {
        int t2 = (tid & 31) * 2;
#pragma unroll
        for (int p=0;p<32;p++) {
            int dd = (tid >> 5) + p*4;
            if (qbase + t2 < NPOS) {
                float2 v = *(const float2*)&Od[dd*68 + t2];
                *(float2*)&out[(ch0 + dd)*NPOS + qbase + t2] = v;
            }
        }
    }
}

// ---------------------------------------------------------------------------
extern "C" void kernel_launch(void* const* d_in, const int* in_sizes, int n_in,
                              void* d_out, int out_size)
{
    const float* fmap = (const float*)d_in[0];
    const float* Wq   = (const float*)d_in[1];
    const float* pf   = (const float*)d_in[2];
    const float* ph   = (const float*)d_in[3];
    const float* pw   = (const float*)d_in[4];
    float* out = (float*)d_out;

    const size_t smemA = (size_t)16384 * sizeof(float);   // 64 KB
    cudaFuncSetAttribute(qkv_kernel, cudaFuncAttributeMaxDynamicSharedMemorySize,
                         (int)smemA);
    dim3 gA(25, 24, BATCH);
    qkv_kernel<<<gA, 128, smemA>>>(fmap, Wq, pf, ph, pw);

    const size_t smemB = (size_t)24576 * sizeof(float);   // 96 KB
    cudaFuncSetAttribute(attn_kernel, cudaFuncAttributeMaxDynamicSharedMemorySize,
                         (int)smemB);
    dim3 gB(25, 32);
    attn_kernel<<<gB, 128, smemB>>>(out);
}

// round 8
// speedup vs baseline: 2.9983x; 1.0001x over previous
#include <cuda_runtime.h>
#include <math.h>
#include <stdint.h>

#define BATCH 8
#define CIN   256
#define NPOS  1568
#define NH    4
#define DH    128

// Scratch layouts:
//  pi(k) = ((k&3)<<2)|((k>>2)&3)           (d-dim of Q/K, 16-groups)
//  rho(j) = 4*((j>>1)&3) + 2*(j>>3) + (j&1) (tok-dim of V, 16-groups)
__device__ float g_q[BATCH*NH*NPOS*DH];   // [bh][tok][pi(d)], *scl*log2e, tf32
__device__ float g_k[BATCH*NH*NPOS*DH];   // [bh][tok][pi(d)], emb folded, tf32
__device__ float g_v[BATCH*NH*DH*NPOS];   // [bh][d][rho(tok)], tf32

__device__ __forceinline__ float to_tf32(float x) {
    uint32_t u;
    asm("cvt.rna.tf32.f32 %0, %1;" : "=r"(u) : "f"(x));
    return __uint_as_float(u);
}
__device__ __forceinline__ float fast_exp2(float x) {
    float y;
    asm("ex2.approx.f32 %0, %1;" : "=f"(y) : "f"(x));
    return y;
}
__device__ __forceinline__ void mma_tf32(float c[4],
        uint32_t a0, uint32_t a1, uint32_t a2, uint32_t a3,
        uint32_t b0, uint32_t b1) {
    asm volatile(
        "mma.sync.aligned.m16n8k8.row.col.f32.tf32.tf32.f32 "
        "{%0,%1,%2,%3}, {%4,%5,%6,%7}, {%8,%9}, {%0,%1,%2,%3};\n"
        : "+f"(c[0]), "+f"(c[1]), "+f"(c[2]), "+f"(c[3])
        : "r"(a0), "r"(a1), "r"(a2), "r"(a3), "r"(b0), "r"(b1));
}
__device__ __forceinline__ void cp16(uint32_t dst, const void* src, bool ok) {
    unsigned sz = ok ? 16u : 0u;
    asm volatile("cp.async.cg.shared.global [%0], [%1], 16, %2;\n"
                 :: "r"(dst), "l"(src), "r"(sz));
}
#define CP_COMMIT()  asm volatile("cp.async.commit_group;\n")
#define CP_WAIT(N)   asm volatile("cp.async.wait_group %0;\n" :: "n"(N))

// ---------------------------------------------------------------------------
// Kernel A: QKV projection via 3xTF32 compensated mma GEMM, with register
// prefetch across the 4 K-chunks. Epilogue: coalesced float4 stores with
// pi (Q/K d-dim) or rho (V tok-dim) folded into the smem gather.
// ---------------------------------------------------------------------------
__global__ __launch_bounds__(128) void qkv_kernel(
    const float* __restrict__ fmap, const float* __restrict__ Wq,
    const float* __restrict__ pf, const float* __restrict__ ph,
    const float* __restrict__ pw)
{
    extern __shared__ float qsm[];
    float* Ah = qsm;            // 64x64, swizzle c4 ^ ((r&7)<<2)
    float* Al = qsm + 4096;
    float* Bh = qsm + 8192;     // 64x64, swizzle c4 ^ ((r&3)<<3)
    float* Bl = qsm + 12288;
    float* Ts = qsm;            // 64x65 epilogue overlay

    const int tid  = threadIdx.x;
    const int lane = tid & 31, w = tid >> 5;
    const int gid  = lane >> 2, tig = lane & 3;
    const int row0 = w*16 + gid;
    const int pbase = blockIdx.x * 64;
    const int obase = blockIdx.y * 64;
    const int b     = blockIdx.z;
    const int g4 = gid & 4, g3 = gid & 3, tsw = tig << 3, ksw = gid << 2;

    const int r0 = tid >> 4, c4l = (tid & 15) * 4;

    float acc[8][4];
#pragma unroll
    for (int nb=0;nb<8;nb++)
#pragma unroll
        for (int c=0;c<4;c++) acc[nb][c] = 0.f;

    float4 ra[8], rb[8];
    {   // prefetch ks=0
#pragma unroll
        for (int p=0;p<8;p++) {
            int r = r0 + p*8;
            ra[p] = *(const float4*)&Wq[(obase + r)*CIN + c4l];
            rb[p] = make_float4(0.f,0.f,0.f,0.f);
            if (pbase + c4l < NPOS)
                rb[p] = *(const float4*)&fmap[(size_t)(b*CIN + r)*NPOS + pbase + c4l];
        }
    }

    for (int ks = 0; ks < 4; ks++) {
        // split & store current chunk
#pragma unroll
        for (int p=0;p<8;p++) {
            int r = r0 + p*8;
            float4 v = ra[p];
            float hx = to_tf32(v.x), hy = to_tf32(v.y), hz = to_tf32(v.z), hw = to_tf32(v.w);
            int o = r*64 + (c4l ^ ((r&7)<<2));
            *(float4*)&Ah[o] = make_float4(hx, hy, hz, hw);
            *(float4*)&Al[o] = make_float4(to_tf32(v.x-hx), to_tf32(v.y-hy),
                                           to_tf32(v.z-hz), to_tf32(v.w-hw));
        }
#pragma unroll
        for (int p=0;p<8;p++) {
            int r = r0 + p*8;
            float4 v = rb[p];
            float hx = to_tf32(v.x), hy = to_tf32(v.y), hz = to_tf32(v.z), hw = to_tf32(v.w);
            int o = r*64 + (c4l ^ ((r&3)<<3));
            *(float4*)&Bh[o] = make_float4(hx, hy, hz, hw);
            *(float4*)&Bl[o] = make_float4(to_tf32(v.x-hx), to_tf32(v.y-hy),
                                           to_tf32(v.z-hz), to_tf32(v.w-hw));
        }
        __syncthreads();

        if (ks < 3) {   // prefetch next chunk (LDG latency hides behind mma)
            int kn = (ks+1)*64;
#pragma unroll
            for (int p=0;p<8;p++) {
                int r = r0 + p*8;
                ra[p] = *(const float4*)&Wq[(obase + r)*CIN + kn + c4l];
                rb[p] = make_float4(0.f,0.f,0.f,0.f);
                if (pbase + c4l < NPOS)
                    rb[p] = *(const float4*)&fmap[(size_t)(b*CIN + kn + r)*NPOS + pbase + c4l];
            }
        }

#pragma unroll
        for (int kc=0; kc<8; kc++) {
            int k0 = kc*8;
            uint32_t ah0 = __float_as_uint(Ah[ row0   *64 + (k0^ksw) + tig]);
            uint32_t ah1 = __float_as_uint(Ah[(row0+8)*64 + (k0^ksw) + tig]);
            uint32_t ah2 = __float_as_uint(Ah[ row0   *64 + ((k0+4)^ksw) + tig]);
            uint32_t ah3 = __float_as_uint(Ah[(row0+8)*64 + ((k0+4)^ksw) + tig]);
            uint32_t al0 = __float_as_uint(Al[ row0   *64 + (k0^ksw) + tig]);
            uint32_t al1 = __float_as_uint(Al[(row0+8)*64 + (k0^ksw) + tig]);
            uint32_t al2 = __float_as_uint(Al[ row0   *64 + ((k0+4)^ksw) + tig]);
            uint32_t al3 = __float_as_uint(Al[(row0+8)*64 + ((k0+4)^ksw) + tig]);
#pragma unroll
            for (int nb=0; nb<8; nb++) {
                int cA = ((nb*8+g4)^tsw) + g3;
                uint32_t bh0 = __float_as_uint(Bh[(k0+tig  )*64 + cA]);
                uint32_t bh1 = __float_as_uint(Bh[(k0+tig+4)*64 + cA]);
                uint32_t bl0 = __float_as_uint(Bl[(k0+tig  )*64 + cA]);
                uint32_t bl1 = __float_as_uint(Bl[(k0+tig+4)*64 + cA]);
                mma_tf32(acc[nb], ah0,ah1,ah2,ah3, bl0,bl1);   // hi*lo
                mma_tf32(acc[nb], al0,al1,al2,al3, bh0,bh1);   // lo*hi
                mma_tf32(acc[nb], ah0,ah1,ah2,ah3, bh0,bh1);   // hi*hi
            }
        }
        __syncthreads();
    }

    // scl * log2(e): attention runs in the exp2 domain
    const float scl = 0.08838834764831845f * 1.4426950408889634f;
    const int sec  = obase >> 9;             // 0=q 1=k 2=v (uniform per tile)
    const int head = (obase >> 7) & 3;
    const int d0   = obase & 127;
    const int bh   = b*NH + head;

    // stage c-frags: Q/K transposed [pos][o]; V direct [o][pos]
    if (sec < 2) {
#pragma unroll
        for (int nb=0;nb<8;nb++)
#pragma unroll
            for (int half=0;half<2;half++)
#pragma unroll
                for (int e=0;e<2;e++)
                    Ts[(nb*8 + 2*tig + e)*65 + row0 + half*8] = acc[nb][half*2+e];
    } else {
#pragma unroll
        for (int nb=0;nb<8;nb++)
#pragma unroll
            for (int half=0;half<2;half++)
#pragma unroll
                for (int e=0;e<2;e++)
                    Ts[(row0 + half*8)*65 + nb*8 + 2*tig + e] = acc[nb][half*2+e];
    }
    __syncthreads();

    const int rr  = tid >> 4;
    const int c4  = (tid & 15) * 4;
    const int tq  = (c4 >> 2) & 3;
    const int cb  = c4 & ~15;
    // pi gather (Q/K d-dim)
    const int lc0 = cb + tq, lc1 = cb + 4 + tq, lc2 = cb + 8 + tq, lc3 = cb + 12 + tq;
    // rho gather (V tok-dim): position 4t+q holds j16 = 2t + 8*(q>>1) + (q&1)
    const int lv0 = cb + 2*tq, lv1 = cb + 2*tq + 1, lv2 = cb + 2*tq + 8, lv3 = cb + 2*tq + 9;

#pragma unroll
    for (int pass=0; pass<8; pass++) {
        int r = rr + pass*8;
        if (sec == 2) {
            if (pbase + c4 < NPOS) {
                float v0 = Ts[r*65+lv0], v1 = Ts[r*65+lv1];
                float v2 = Ts[r*65+lv2], v3 = Ts[r*65+lv3];
                *(float4*)&g_v[((size_t)bh*DH + d0 + r)*NPOS + pbase + c4] =
                    make_float4(to_tf32(v0), to_tf32(v1), to_tf32(v2), to_tf32(v3));
            }
        } else {
            float v0 = Ts[r*65+lc0], v1 = Ts[r*65+lc1];
            float v2 = Ts[r*65+lc2], v3 = Ts[r*65+lc3];
            int pos = pbase + r;
            if (pos < NPOS) {
                size_t o_ = ((size_t)bh*NPOS + pos)*DH + d0 + c4;
                if (sec == 0) {
                    *(float4*)&g_q[o_] = make_float4(
                        to_tf32(v0*scl), to_tf32(v1*scl), to_tf32(v2*scl), to_tf32(v3*scl));
                } else {
                    int f_ = pos / 196; int rem = pos - f_*196;
                    int h_ = rem / 14;  int w_  = rem - h_*14;
                    const float* pfr = pf + f_*DH + d0;
                    const float* phr = ph + h_*DH + d0;
                    const float* pwr = pw + w_*DH + d0;
                    *(float4*)&g_k[o_] = make_float4(
                        to_tf32(v0 + pfr[lc0] + phr[lc0] + pwr[lc0]),
                        to_tf32(v1 + pfr[lc1] + phr[lc1] + pwr[lc1]),
                        to_tf32(v2 + pfr[lc2] + phr[lc2] + pwr[lc2]),
                        to_tf32(v3 + pfr[lc3] + phr[lc3] + pwr[lc3]));
                }
            }
        }
    }
}

// ---------------------------------------------------------------------------
// Kernel B: flash attention. S c-frags feed PV mma DIRECTLY as A-frags
// (k-permutation sigma folded into V's rho token layout) — no shuffles, no
// P smem. exp2-domain softmax. cp.async double-buffered K + pipelined V.
// ---------------------------------------------------------------------------
__global__ __launch_bounds__(128, 2) void attn_kernel(float* __restrict__ out)
{
    extern __shared__ float sm[];
    float* Kb[2] = { sm, sm + 8192 };
    float* Vb    = sm + 16384;         // [d=128][rho(tok)=64]
    float* Od    = sm;                 // 128 x 68 overlay

    const int tid  = threadIdx.x;
    const int lane = tid & 31, w = tid >> 5;
    const int gid  = lane >> 2, tig = lane & 3;
    const int qt = blockIdx.x, bh = blockIdx.y;
    const int qbase = qt * 64;
    const int row0 = w*16 + gid;
    const int gsw = gid << 4;
    const int vsw = (gid & 3) << 4;

    const float* qp = g_q + (size_t)bh * NPOS * DH;
    const float* kp = g_k + (size_t)bh * NPOS * DH;
    const float* vp = g_v + (size_t)bh * DH * NPOS;

    {
        int r0 = tid >> 5; int c4 = (tid & 31) * 4;
#pragma unroll
        for (int p=0;p<16;p++) {
            int r = r0 + p*4;
            float4 v = make_float4(0.f,0.f,0.f,0.f);
            if (qbase + r < NPOS) v = *(const float4*)&qp[(size_t)(qbase + r)*DH + c4];
            *(float4*)&Kb[0][r*128 + (c4 ^ ((r&7)<<4))] = v;
        }
    }
    __syncthreads();
    uint32_t qa[16][4];
#pragma unroll
    for (int kpi=0;kpi<8;kpi++) {
        float4 r0 = *(const float4*)&Kb[0][ row0   *128 + ((kpi*16) ^ gsw) + tig*4];
        float4 r1 = *(const float4*)&Kb[0][(row0+8)*128 + ((kpi*16) ^ gsw) + tig*4];
        qa[2*kpi  ][0] = __float_as_uint(r0.x); qa[2*kpi  ][1] = __float_as_uint(r1.x);
        qa[2*kpi  ][2] = __float_as_uint(r0.y); qa[2*kpi  ][3] = __float_as_uint(r1.y);
        qa[2*kpi+1][0] = __float_as_uint(r0.z); qa[2*kpi+1][1] = __float_as_uint(r1.z);
        qa[2*kpi+1][2] = __float_as_uint(r0.w); qa[2*kpi+1][3] = __float_as_uint(r1.w);
    }
    __syncthreads();

    const uint32_t smK0 = (uint32_t)__cvta_generic_to_shared(Kb[0]);
    const uint32_t smK1 = (uint32_t)__cvta_generic_to_shared(Kb[1]);
    const uint32_t smV  = (uint32_t)__cvta_generic_to_shared(Vb);
    const int lr0 = tid >> 5, lc4 = (tid & 31) * 4;
    const int vr0 = tid >> 4, vc4 = (tid & 15) * 4;

#pragma unroll
    for (int p=0;p<16;p++) {
        int r = lr0 + p*4;
        cp16(smK0 + (r*128 + (lc4 ^ ((r&7)<<4)))*4, &kp[(size_t)r*DH + lc4], r < NPOS);
    }
    CP_COMMIT();
#pragma unroll
    for (int p=0;p<16;p++) {
        int r = vr0 + p*8;
        cp16(smV + (r*64 + (vc4 ^ ((r&3)<<4)))*4, &vp[(size_t)r*NPOS + vc4], vc4 < NPOS);
    }
    CP_COMMIT();

    float m0=-1e30f, m1=-1e30f, l0=0.f, l1=0.f;
    float O[16][4];
#pragma unroll
    for (int nb=0;nb<16;nb++)
#pragma unroll
        for (int c=0;c<4;c++) O[nb][c] = 0.f;

    for (int t = 0; t < 25; t++) {
        const int kb = t * 64;
        const float* Ks = Kb[t & 1];
        CP_WAIT(1);
        __syncthreads();

        float S[8][4];
#pragma unroll
        for (int nb=0;nb<8;nb++)
#pragma unroll
            for (int c=0;c<4;c++) S[nb][c] = 0.f;
#pragma unroll
        for (int kpi=0;kpi<8;kpi++) {
#pragma unroll
            for (int nb=0;nb<8;nb++) {
                int rr = nb*8 + gid;
                float4 kv = *(const float4*)&Ks[rr*128 + ((kpi*16) ^ gsw) + tig*4];
                mma_tf32(S[nb], qa[2*kpi  ][0],qa[2*kpi  ][1],qa[2*kpi  ][2],qa[2*kpi  ][3],
                         __float_as_uint(kv.x), __float_as_uint(kv.y));
                mma_tf32(S[nb], qa[2*kpi+1][0],qa[2*kpi+1][1],qa[2*kpi+1][2],qa[2*kpi+1][3],
                         __float_as_uint(kv.z), __float_as_uint(kv.w));
            }
        }

        {
            int tn = (t+1 < 25) ? t+1 : 24;
            const float* kpn = kp + (size_t)tn*64*DH;
            uint32_t dstK = (t & 1) ? smK0 : smK1;
#pragma unroll
            for (int p=0;p<16;p++) {
                int r = lr0 + p*4;
                cp16(dstK + (r*128 + (lc4 ^ ((r&7)<<4)))*4,
                     &kpn[(size_t)r*DH + lc4], tn*64 + r < NPOS);
            }
            CP_COMMIT();
        }

        if (kb + 64 > NPOS) {
#pragma unroll
            for (int nb=0;nb<8;nb++) {
                int c0 = kb + nb*8 + 2*tig;
                if (c0     >= NPOS) { S[nb][0] = -1e30f; S[nb][2] = -1e30f; }
                if (c0 + 1 >= NPOS) { S[nb][1] = -1e30f; S[nb][3] = -1e30f; }
            }
        }

        // ---- online softmax (log2 domain: S already scaled by log2e) ----
        float mx0 = -1e30f, mx1 = -1e30f;
#pragma unroll
        for (int nb=0;nb<8;nb++) {
            mx0 = fmaxf(mx0, fmaxf(S[nb][0], S[nb][1]));
            mx1 = fmaxf(mx1, fmaxf(S[nb][2], S[nb][3]));
        }
        mx0 = fmaxf(mx0, __shfl_xor_sync(0xffffffffu, mx0, 1));
        mx0 = fmaxf(mx0, __shfl_xor_sync(0xffffffffu, mx0, 2));
        mx1 = fmaxf(mx1, __shfl_xor_sync(0xffffffffu, mx1, 1));
        mx1 = fmaxf(mx1, __shfl_xor_sync(0xffffffffu, mx1, 2));
        float mn0 = fmaxf(m0, mx0), mn1 = fmaxf(m1, mx1);
        float corr0 = fast_exp2(m0 - mn0), corr1 = fast_exp2(m1 - mn1);
        m0 = mn0; m1 = mn1;
        float rs0 = 0.f, rs1 = 0.f;
#pragma unroll
        for (int nb=0;nb<8;nb++) {
            S[nb][0] = fast_exp2(S[nb][0] - m0); rs0 += S[nb][0];
            S[nb][1] = fast_exp2(S[nb][1] - m0); rs0 += S[nb][1];
            S[nb][2] = fast_exp2(S[nb][2] - m1); rs1 += S[nb][2];
            S[nb][3] = fast_exp2(S[nb][3] - m1); rs1 += S[nb][3];
        }
        rs0 += __shfl_xor_sync(0xffffffffu, rs0, 1);
        rs0 += __shfl_xor_sync(0xffffffffu, rs0, 2);
        rs1 += __shfl_xor_sync(0xffffffffu, rs1, 1);
        rs1 += __shfl_xor_sync(0xffffffffu, rs1, 2);
        l0 = l0*corr0 + rs0;
        l1 = l1*corr1 + rs1;
        // skip the O rescale when nothing changed (corr==1 for whole warp)
        unsigned vote = __ballot_sync(0xffffffffu,
                                      (corr0 == 1.f) && (corr1 == 1.f));
        if (vote != 0xffffffffu) {
#pragma unroll
            for (int nb=0;nb<16;nb++) {
                O[nb][0] *= corr0; O[nb][1] *= corr0;
                O[nb][2] *= corr1; O[nb][3] *= corr1;
            }
        }

        CP_WAIT(1);
        __syncthreads();

        // ---- O += P V : S c-frags ARE the A-frags (sigma/rho layout) ----
#pragma unroll
        for (int kpi=0;kpi<4;kpi++) {
            int e = 2*kpi, o = 2*kpi+1;
            uint32_t ea0 = __float_as_uint(to_tf32(S[e][0]));
            uint32_t ea1 = __float_as_uint(to_tf32(S[e][2]));
            uint32_t ea2 = __float_as_uint(to_tf32(S[e][1]));
            uint32_t ea3 = __float_as_uint(to_tf32(S[e][3]));
            uint32_t oa0 = __float_as_uint(to_tf32(S[o][0]));
            uint32_t oa1 = __float_as_uint(to_tf32(S[o][2]));
            uint32_t oa2 = __float_as_uint(to_tf32(S[o][1]));
            uint32_t oa3 = __float_as_uint(to_tf32(S[o][3]));
#pragma unroll
            for (int nb=0;nb<16;nb++) {
                int rr = nb*8 + gid;
                float4 vv = *(const float4*)&Vb[rr*64 + ((kpi*16) ^ vsw) + tig*4];
                mma_tf32(O[nb], ea0,ea1,ea2,ea3,
                         __float_as_uint(vv.x), __float_as_uint(vv.y));
                mma_tf32(O[nb], oa0,oa1,oa2,oa3,
                         __float_as_uint(vv.z), __float_as_uint(vv.w));
            }
        }
        __syncthreads();

        {
            int tn = (t+1 < 25) ? t+1 : 24;
            const float* vpn = vp + (size_t)tn*64;
#pragma unroll
            for (int p=0;p<16;p++) {
                int r = vr0 + p*8;
                cp16(smV + (r*64 + (vc4 ^ ((r&3)<<4)))*4,
                     &vpn[(size_t)r*NPOS + vc4], tn*64 + vc4 < NPOS);
            }
            CP_COMMIT();
        }
    }

    CP_WAIT(0);
    __syncthreads();
    float inv0 = 1.0f / l0, inv1 = 1.0f / l1;
#pragma unroll
    for (int nb=0;nb<16;nb++) {
        Od[(nb*8 + 2*tig    )*68 + row0    ] = O[nb][0] * inv0;
        Od[(nb*8 + 2*tig + 1)*68 + row0    ] = O[nb][1] * inv0;
        Od[(nb*8 + 2*tig    )*68 + row0 + 8] = O[nb][2] * inv1;
        Od[(nb*8 + 2*tig + 1)*68 + row0 + 8] = O[nb][3] * inv1;
    }
    __syncthreads();

    const int b = bh >> 2, head = bh & 3;
    const size_t ch0 = (size_t)b*512 + head*128;
    {
        int t2 = (tid & 31) * 2;
#pragma unroll
        for (int p=0;p<32;p++) {
            int dd = (tid >> 5) + p*4;
            if (qbase + t2 < NPOS) {
                float2 v = *(const float2*)&Od[dd*68 + t2];
                *(float2*)&out[(ch0 + dd)*NPOS + qbase + t2] = v;
            }
        }
    }
}

// ---------------------------------------------------------------------------
extern "C" void kernel_launch(void* const* d_in, const int* in_sizes, int n_in,
                              void* d_out, int out_size)
{
    const float* fmap = (const float*)d_in[0];
    const float* Wq   = (const float*)d_in[1];
    const float* pf   = (const float*)d_in[2];
    const float* ph   = (const float*)d_in[3];
    const float* pw   = (const float*)d_in[4];
    float* out = (float*)d_out;

    const size_t smemA = (size_t)16384 * sizeof(float);   // 64 KB
    cudaFuncSetAttribute(qkv_kernel, cudaFuncAttributeMaxDynamicSharedMemorySize,
                         (int)smemA);
    dim3 gA(25, 24, BATCH);
    qkv_kernel<<<gA, 128, smemA>>>(fmap, Wq, pf, ph, pw);

    const size_t smemB = (size_t)24576 * sizeof(float);   // 96 KB
    cudaFuncSetAttribute(attn_kernel, cudaFuncAttributeMaxDynamicSharedMemorySize,
                         (int)smemB);
    dim3 gB(25, 32);
    attn_kernel<<<gB, 128, smemB>>>(out);
}

// round 10
// speedup vs baseline: 3.0958x; 1.0325x over previous
#include <cuda_runtime.h>
#include <math.h>
#include <stdint.h>

#define BATCH 8
#define CIN   256
#define NPOS  1568
#define NH    4
#define DH    128

// Scratch layouts:
//  pi(k) = ((k&3)<<2)|((k>>2)&3)           (d-dim of Q/K, 16-groups)
//  rho(j) = 4*((j>>1)&3) + 2*(j>>3) + (j&1) (tok-dim of V, 16-groups)
__device__ float g_q[BATCH*NH*NPOS*DH];   // [bh][tok][pi(d)], *scl*log2e, tf32
__device__ float g_k[BATCH*NH*NPOS*DH];   // [bh][tok][pi(d)], emb folded, tf32
__device__ float g_v[BATCH*NH*DH*NPOS];   // [bh][d][rho(tok)], tf32

__device__ __forceinline__ float to_tf32(float x) {
    uint32_t u; asm("cvt.rna.tf32.f32 %0, %1;" : "=r"(u) : "f"(x));
    return __uint_as_float(u);
}
__device__ __forceinline__ float fast_exp2(float x) {
    float y; asm("ex2.approx.f32 %0, %1;" : "=f"(y) : "f"(x)); return y;
}
__device__ __forceinline__ void mma_tf32(float c[4],
        uint32_t a0, uint32_t a1, uint32_t a2, uint32_t a3,
        uint32_t b0, uint32_t b1) {
    asm volatile(
        "mma.sync.aligned.m16n8k8.row.col.f32.tf32.tf32.f32 "
        "{%0,%1,%2,%3}, {%4,%5,%6,%7}, {%8,%9}, {%0,%1,%2,%3};\n"
        : "+f"(c[0]), "+f"(c[1]), "+f"(c[2]), "+f"(c[3])
        : "r"(a0), "r"(a1), "r"(a2), "r"(a3), "r"(b0), "r"(b1));
}
__device__ __forceinline__ void cp16(uint32_t dst, const void* src, bool ok) {
    unsigned sz = ok ? 16u : 0u;
    asm volatile("cp.async.cg.shared.global [%0], [%1], 16, %2;\n"
                 :: "r"(dst), "l"(src), "r"(sz));
}
#define CP_COMMIT()  asm volatile("cp.async.commit_group;\n")
#define CP_WAIT(N)   asm volatile("cp.async.wait_group %0;\n" :: "n"(N))

// ---------------------------------------------------------------------------
// Kernel A: QKV projection via 3xTF32 compensated mma GEMM, with register
// prefetch across the 4 K-chunks. Epilogue: coalesced float4 stores with
// pi (Q/K d-dim) or rho (V tok-dim) folded into the smem gather.
// ---------------------------------------------------------------------------
__global__ __launch_bounds__(128) void qkv_kernel(
    const float* __restrict__ fmap, const float* __restrict__ Wq,
    const float* __restrict__ pf, const float* __restrict__ ph,
    const float* __restrict__ pw)
{
    extern __shared__ float qsm[];
    float* Ah = qsm;            // 64x64, swizzle c4 ^ ((r&7)<<2)
    float* Al = qsm + 4096;
    float* Bh = qsm + 8192;     // 64x64, swizzle c4 ^ ((r&3)<<3)
    float* Bl = qsm + 12288;
    float* Ts = qsm;            // 64x65 epilogue overlay

    const int tid  = threadIdx.x;
    const int lane = tid & 31, w = tid >> 5;
    const int gid  = lane >> 2, tig = lane & 3;
    const int row0 = w*16 + gid;
    const int pbase = blockIdx.x * 64;
    const int obase = blockIdx.y * 64;
    const int b     = blockIdx.z;
    const int g4 = gid & 4, g3 = gid & 3, tsw = tig << 3, ksw = gid << 2;
    const int r0 = tid >> 4, c4l = (tid & 15) * 4;

    float acc[8][4];
#pragma unroll
    for (int nb=0;nb<8;nb++)
#pragma unroll
        for (int c=0;c<4;c++) acc[nb][c] = 0.f;

    float4 ra[8], rb[8];
#pragma unroll
    for (int p=0;p<8;p++) {
        int r = r0 + p*8;
        ra[p] = *(const float4*)&Wq[(obase + r)*CIN + c4l];
        rb[p] = make_float4(0.f,0.f,0.f,0.f);
        if (pbase + c4l < NPOS)
            rb[p] = *(const float4*)&fmap[(size_t)(b*CIN + r)*NPOS + pbase + c4l];
    }

    for (int ks = 0; ks < 4; ks++) {
#pragma unroll
        for (int p=0;p<8;p++) {
            int r = r0 + p*8;
            float4 v = ra[p];
            float hx = to_tf32(v.x), hy = to_tf32(v.y), hz = to_tf32(v.z), hw = to_tf32(v.w);
            int o = r*64 + (c4l ^ ((r&7)<<2));
            *(float4*)&Ah[o] = make_float4(hx, hy, hz, hw);
            *(float4*)&Al[o] = make_float4(to_tf32(v.x-hx), to_tf32(v.y-hy),
                                           to_tf32(v.z-hz), to_tf32(v.w-hw));
        }
#pragma unroll
        for (int p=0;p<8;p++) {
            int r = r0 + p*8;
            float4 v = rb[p];
            float hx = to_tf32(v.x), hy = to_tf32(v.y), hz = to_tf32(v.z), hw = to_tf32(v.w);
            int o = r*64 + (c4l ^ ((r&3)<<3));
            *(float4*)&Bh[o] = make_float4(hx, hy, hz, hw);
            *(float4*)&Bl[o] = make_float4(to_tf32(v.x-hx), to_tf32(v.y-hy),
                                           to_tf32(v.z-hz), to_tf32(v.w-hw));
        }
        __syncthreads();

        if (ks < 3) {
            int kn = (ks+1)*64;
#pragma unroll
            for (int p=0;p<8;p++) {
                int r = r0 + p*8;
                ra[p] = *(const float4*)&Wq[(obase + r)*CIN + kn + c4l];
                rb[p] = make_float4(0.f,0.f,0.f,0.f);
                if (pbase + c4l < NPOS)
                    rb[p] = *(const float4*)&fmap[(size_t)(b*CIN + kn + r)*NPOS + pbase + c4l];
            }
        }

#pragma unroll
        for (int kc=0; kc<8; kc++) {
            int k0 = kc*8;
            uint32_t ah0 = __float_as_uint(Ah[ row0   *64 + (k0^ksw) + tig]);
            uint32_t ah1 = __float_as_uint(Ah[(row0+8)*64 + (k0^ksw) + tig]);
            uint32_t ah2 = __float_as_uint(Ah[ row0   *64 + ((k0+4)^ksw) + tig]);
            uint32_t ah3 = __float_as_uint(Ah[(row0+8)*64 + ((k0+4)^ksw) + tig]);
            uint32_t al0 = __float_as_uint(Al[ row0   *64 + (k0^ksw) + tig]);
            uint32_t al1 = __float_as_uint(Al[(row0+8)*64 + (k0^ksw) + tig]);
            uint32_t al2 = __float_as_uint(Al[ row0   *64 + ((k0+4)^ksw) + tig]);
            uint32_t al3 = __float_as_uint(Al[(row0+8)*64 + ((k0+4)^ksw) + tig]);
#pragma unroll
            for (int nb=0; nb<8; nb++) {
                int cA = ((nb*8+g4)^tsw) + g3;
                uint32_t bh0 = __float_as_uint(Bh[(k0+tig  )*64 + cA]);
                uint32_t bh1 = __float_as_uint(Bh[(k0+tig+4)*64 + cA]);
                uint32_t bl0 = __float_as_uint(Bl[(k0+tig  )*64 + cA]);
                uint32_t bl1 = __float_as_uint(Bl[(k0+tig+4)*64 + cA]);
                mma_tf32(acc[nb], ah0,ah1,ah2,ah3, bl0,bl1);   // hi*lo
                mma_tf32(acc[nb], al0,al1,al2,al3, bh0,bh1);   // lo*hi
                mma_tf32(acc[nb], ah0,ah1,ah2,ah3, bh0,bh1);   // hi*hi
            }
        }
        __syncthreads();
    }

    // scl * log2(e): attention runs in the exp2 domain
    const float scl = 0.08838834764831845f * 1.4426950408889634f;
    const int sec  = obase >> 9;             // 0=q 1=k 2=v (uniform per tile)
    const int head = (obase >> 7) & 3;
    const int d0   = obase & 127;
    const int bh   = b*NH + head;

    if (sec < 2) {
#pragma unroll
        for (int nb=0;nb<8;nb++)
#pragma unroll
            for (int half=0;half<2;half++)
#pragma unroll
                for (int e=0;e<2;e++)
                    Ts[(nb*8 + 2*tig + e)*65 + row0 + half*8] = acc[nb][half*2+e];
    } else {
#pragma unroll
        for (int nb=0;nb<8;nb++)
#pragma unroll
            for (int half=0;half<2;half++)
#pragma unroll
                for (int e=0;e<2;e++)
                    Ts[(row0 + half*8)*65 + nb*8 + 2*tig + e] = acc[nb][half*2+e];
    }
    __syncthreads();

    const int rr  = tid >> 4;
    const int c4  = (tid & 15) * 4;
    const int tq  = (c4 >> 2) & 3;
    const int cb  = c4 & ~15;
    // pi gather (Q/K d-dim)
    const int lc0 = cb + tq, lc1 = cb + 4 + tq, lc2 = cb + 8 + tq, lc3 = cb + 12 + tq;
    // rho gather (V tok-dim)
    const int lv0 = cb + 2*tq, lv1 = cb + 2*tq + 1, lv2 = cb + 2*tq + 8, lv3 = cb + 2*tq + 9;

#pragma unroll
    for (int pass=0; pass<8; pass++) {
        int r = rr + pass*8;
        if (sec == 2) {
            if (pbase + c4 < NPOS) {
                float v0 = Ts[r*65+lv0], v1 = Ts[r*65+lv1];
                float v2 = Ts[r*65+lv2], v3 = Ts[r*65+lv3];
                *(float4*)&g_v[((size_t)bh*DH + d0 + r)*NPOS + pbase + c4] =
                    make_float4(to_tf32(v0), to_tf32(v1), to_tf32(v2), to_tf32(v3));
            }
        } else {
            float v0 = Ts[r*65+lc0], v1 = Ts[r*65+lc1];
            float v2 = Ts[r*65+lc2], v3 = Ts[r*65+lc3];
            int pos = pbase + r;
            if (pos < NPOS) {
                size_t o_ = ((size_t)bh*NPOS + pos)*DH + d0 + c4;
                if (sec == 0) {
                    *(float4*)&g_q[o_] = make_float4(
                        to_tf32(v0*scl), to_tf32(v1*scl), to_tf32(v2*scl), to_tf32(v3*scl));
                } else {
                    int f_ = pos / 196; int rem = pos - f_*196;
                    int h_ = rem / 14;  int w_  = rem - h_*14;
                    const float* pfr = pf + f_*DH + d0;
                    const float* phr = ph + h_*DH + d0;
                    const float* pwr = pw + w_*DH + d0;
                    *(float4*)&g_k[o_] = make_float4(
                        to_tf32(v0 + pfr[lc0] + phr[lc0] + pwr[lc0]),
                        to_tf32(v1 + pfr[lc1] + phr[lc1] + pwr[lc1]),
                        to_tf32(v2 + pfr[lc2] + phr[lc2] + pwr[lc2]),
                        to_tf32(v3 + pfr[lc3] + phr[lc3] + pwr[lc3]));
                }
            }
        }
    }
}

// ---------------------------------------------------------------------------
// Kernel B: flash attention, tf32 mma, FIXED-reference-max softmax:
// row max computed once on tile 0; later tiles are pure elementwise exp2
// (no shuffles, no corr, no O rescale; l reduced once after the loop).
// S c-frags feed PV mma directly as A-frags (sigma/rho layout).
// ---------------------------------------------------------------------------
__global__ __launch_bounds__(128, 2) void attn_kernel(float* __restrict__ out)
{
    extern __shared__ float sm[];
    float* Kb[2] = { sm, sm + 8192 };
    float* Vb    = sm + 16384;         // [d=128][rho(tok)=64]
    float* Od    = sm;                 // 128 x 68 overlay

    const int tid  = threadIdx.x;
    const int lane = tid & 31, w = tid >> 5;
    const int gid  = lane >> 2, tig = lane & 3;
    const int qt = blockIdx.x, bh = blockIdx.y;
    const int qbase = qt * 64;
    const int row0 = w*16 + gid;
    const int gsw = gid << 4;
    const int vsw = (gid & 3) << 4;

    const float* qp = g_q + (size_t)bh * NPOS * DH;
    const float* kp = g_k + (size_t)bh * NPOS * DH;
    const float* vp = g_v + (size_t)bh * DH * NPOS;

    {
        int r0 = tid >> 5; int c4 = (tid & 31) * 4;
#pragma unroll
        for (int p=0;p<16;p++) {
            int r = r0 + p*4;
            float4 v = make_float4(0.f,0.f,0.f,0.f);
            if (qbase + r < NPOS) v = *(const float4*)&qp[(size_t)(qbase + r)*DH + c4];
            *(float4*)&Kb[0][r*128 + (c4 ^ ((r&7)<<4))] = v;
        }
    }
    __syncthreads();
    uint32_t qa[16][4];
#pragma unroll
    for (int kpi=0;kpi<8;kpi++) {
        float4 r0 = *(const float4*)&Kb[0][ row0   *128 + ((kpi*16) ^ gsw) + tig*4];
        float4 r1 = *(const float4*)&Kb[0][(row0+8)*128 + ((kpi*16) ^ gsw) + tig*4];
        qa[2*kpi  ][0] = __float_as_uint(r0.x); qa[2*kpi  ][1] = __float_as_uint(r1.x);
        qa[2*kpi  ][2] = __float_as_uint(r0.y); qa[2*kpi  ][3] = __float_as_uint(r1.y);
        qa[2*kpi+1][0] = __float_as_uint(r0.z); qa[2*kpi+1][1] = __float_as_uint(r1.z);
        qa[2*kpi+1][2] = __float_as_uint(r0.w); qa[2*kpi+1][3] = __float_as_uint(r1.w);
    }
    __syncthreads();

    const uint32_t smK0 = (uint32_t)__cvta_generic_to_shared(Kb[0]);
    const uint32_t smK1 = (uint32_t)__cvta_generic_to_shared(Kb[1]);
    const uint32_t smV  = (uint32_t)__cvta_generic_to_shared(Vb);
    const int lr0 = tid >> 5, lc4 = (tid & 31) * 4;
    const int vr0 = tid >> 4, vc4 = (tid & 15) * 4;

#pragma unroll
    for (int p=0;p<16;p++) {
        int r = lr0 + p*4;
        cp16(smK0 + (r*128 + (lc4 ^ ((r&7)<<4)))*4, &kp[(size_t)r*DH + lc4], r < NPOS);
    }
    CP_COMMIT();
#pragma unroll
    for (int p=0;p<16;p++) {
        int r = vr0 + p*8;
        cp16(smV + (r*64 + (vc4 ^ ((r&3)<<4)))*4, &vp[(size_t)r*NPOS + vc4], vc4 < NPOS);
    }
    CP_COMMIT();

    float m0 = 0.f, m1 = 0.f;       // fixed per-row reference (set at t==0)
    float l0 = 0.f, l1 = 0.f;       // lane-private partial sums (quad-reduced at end)
    float O[16][4];
#pragma unroll
    for (int nb=0;nb<16;nb++)
#pragma unroll
        for (int c=0;c<4;c++) O[nb][c] = 0.f;

    for (int t = 0; t < 25; t++) {
        const int kb = t * 64;
        const float* Ks = Kb[t & 1];
        CP_WAIT(1);
        __syncthreads();

        float S[8][4];
#pragma unroll
        for (int nb=0;nb<8;nb++)
#pragma unroll
            for (int c=0;c<4;c++) S[nb][c] = 0.f;
#pragma unroll
        for (int kpi=0;kpi<8;kpi++) {
#pragma unroll
            for (int nb=0;nb<8;nb++) {
                int rr = nb*8 + gid;
                float4 kv = *(const float4*)&Ks[rr*128 + ((kpi*16) ^ gsw) + tig*4];
                mma_tf32(S[nb], qa[2*kpi  ][0],qa[2*kpi  ][1],qa[2*kpi  ][2],qa[2*kpi  ][3],
                         __float_as_uint(kv.x), __float_as_uint(kv.y));
                mma_tf32(S[nb], qa[2*kpi+1][0],qa[2*kpi+1][1],qa[2*kpi+1][2],qa[2*kpi+1][3],
                         __float_as_uint(kv.z), __float_as_uint(kv.w));
            }
        }

        {
            int tn = (t+1 < 25) ? t+1 : 24;
            const float* kpn = kp + (size_t)tn*64*DH;
            uint32_t dstK = (t & 1) ? smK0 : smK1;
#pragma unroll
            for (int p=0;p<16;p++) {
                int r = lr0 + p*4;
                cp16(dstK + (r*128 + (lc4 ^ ((r&7)<<4)))*4,
                     &kpn[(size_t)r*DH + lc4], tn*64 + r < NPOS);
            }
            CP_COMMIT();
        }

        if (kb + 64 > NPOS) {
#pragma unroll
            for (int nb=0;nb<8;nb++) {
                int c0 = kb + nb*8 + 2*tig;
                if (c0     >= NPOS) { S[nb][0] = -1e30f; S[nb][2] = -1e30f; }
                if (c0 + 1 >= NPOS) { S[nb][1] = -1e30f; S[nb][3] = -1e30f; }
            }
        }

        if (t == 0) {
            // one-time per-row reference max (tile 0, full 64 keys, no mask)
            float mx0 = -1e30f, mx1 = -1e30f;
#pragma unroll
            for (int nb=0;nb<8;nb++) {
                mx0 = fmaxf(mx0, fmaxf(S[nb][0], S[nb][1]));
                mx1 = fmaxf(mx1, fmaxf(S[nb][2], S[nb][3]));
            }
            mx0 = fmaxf(mx0, __shfl_xor_sync(0xffffffffu, mx0, 1));
            mx0 = fmaxf(mx0, __shfl_xor_sync(0xffffffffu, mx0, 2));
            mx1 = fmaxf(mx1, __shfl_xor_sync(0xffffffffu, mx1, 1));
            mx1 = fmaxf(mx1, __shfl_xor_sync(0xffffffffu, mx1, 2));
            m0 = mx0; m1 = mx1;
        }

        // ---- elementwise exp2 vs fixed reference; lane-private l partials ----
        float rs0 = 0.f, rs1 = 0.f;
#pragma unroll
        for (int nb=0;nb<8;nb++) {
            S[nb][0] = fast_exp2(S[nb][0] - m0); rs0 += S[nb][0];
            S[nb][1] = fast_exp2(S[nb][1] - m0); rs0 += S[nb][1];
            S[nb][2] = fast_exp2(S[nb][2] - m1); rs1 += S[nb][2];
            S[nb][3] = fast_exp2(S[nb][3] - m1); rs1 += S[nb][3];
        }
        l0 += rs0;
        l1 += rs1;

        CP_WAIT(1);
        __syncthreads();

        // ---- O += P V : S c-frags ARE the A-frags (sigma/rho layout) ----
#pragma unroll
        for (int kpi=0;kpi<4;kpi++) {
            int e = 2*kpi, o = 2*kpi+1;
            uint32_t ea0 = __float_as_uint(to_tf32(S[e][0]));
            uint32_t ea1 = __float_as_uint(to_tf32(S[e][2]));
            uint32_t ea2 = __float_as_uint(to_tf32(S[e][1]));
            uint32_t ea3 = __float_as_uint(to_tf32(S[e][3]));
            uint32_t oa0 = __float_as_uint(to_tf32(S[o][0]));
            uint32_t oa1 = __float_as_uint(to_tf32(S[o][2]));
            uint32_t oa2 = __float_as_uint(to_tf32(S[o][1]));
            uint32_t oa3 = __float_as_uint(to_tf32(S[o][3]));
#pragma unroll
            for (int nb=0;nb<16;nb++) {
                int rr = nb*8 + gid;
                float4 vv = *(const float4*)&Vb[rr*64 + ((kpi*16) ^ vsw) + tig*4];
                mma_tf32(O[nb], ea0,ea1,ea2,ea3,
                         __float_as_uint(vv.x), __float_as_uint(vv.y));
                mma_tf32(O[nb], oa0,oa1,oa2,oa3,
                         __float_as_uint(vv.z), __float_as_uint(vv.w));
            }
        }
        __syncthreads();

        {
            int tn = (t+1 < 25) ? t+1 : 24;
            const float* vpn = vp + (size_t)tn*64;
#pragma unroll
            for (int p=0;p<16;p++) {
                int r = vr0 + p*8;
                cp16(smV + (r*64 + (vc4 ^ ((r&3)<<4)))*4,
                     &vpn[(size_t)r*NPOS + vc4], tn*64 + vc4 < NPOS);
            }
            CP_COMMIT();
        }
    }

    // ---- one-time l reduction across the quad ----
    l0 += __shfl_xor_sync(0xffffffffu, l0, 1);
    l0 += __shfl_xor_sync(0xffffffffu, l0, 2);
    l1 += __shfl_xor_sync(0xffffffffu, l1, 1);
    l1 += __shfl_xor_sync(0xffffffffu, l1, 2);

    CP_WAIT(0);
    __syncthreads();
    float inv0 = 1.0f / l0, inv1 = 1.0f / l1;
#pragma unroll
    for (int nb=0;nb<16;nb++) {
        Od[(nb*8 + 2*tig    )*68 + row0    ] = O[nb][0] * inv0;
        Od[(nb*8 + 2*tig + 1)*68 + row0    ] = O[nb][1] * inv0;
        Od[(nb*8 + 2*tig    )*68 + row0 + 8] = O[nb][2] * inv1;
        Od[(nb*8 + 2*tig + 1)*68 + row0 + 8] = O[nb][3] * inv1;
    }
    __syncthreads();

    const int b = bh >> 2, head = bh & 3;
    const size_t ch0 = (size_t)b*512 + head*128;
    {
        int t2 = (tid & 31) * 2;
#pragma unroll
        for (int p=0;p<32;p++) {
            int dd = (tid >> 5) + p*4;
            if (qbase + t2 < NPOS) {
                float2 v = *(const float2*)&Od[dd*68 + t2];
                *(float2*)&out[(ch0 + dd)*NPOS + qbase + t2] = v;
            }
        }
    }
}

// ---------------------------------------------------------------------------
extern "C" void kernel_launch(void* const* d_in, const int* in_sizes, int n_in,
                              void* d_out, int out_size)
{
    const float* fmap = (const float*)d_in[0];
    const float* Wq   = (const float*)d_in[1];
    const float* pf   = (const float*)d_in[2];
    const float* ph   = (const float*)d_in[3];
    const float* pw   = (const float*)d_in[4];
    float* out = (float*)d_out;

    const size_t smemA = (size_t)16384 * sizeof(float);   // 64 KB
    cudaFuncSetAttribute(qkv_kernel, cudaFuncAttributeMaxDynamicSharedMemorySize,
                         (int)smemA);
    dim3 gA(25, 24, BATCH);
    qkv_kernel<<<gA, 128, smemA>>>(fmap, Wq, pf, ph, pw);

    const size_t smemB = (size_t)24576 * sizeof(float);   // 96 KB
    cudaFuncSetAttribute(attn_kernel, cudaFuncAttributeMaxDynamicSharedMemorySize,
                         (int)smemB);
    dim3 gB(25, 32);
    attn_kernel<<<gB, 128, smemB>>>(out);
}

// round 12
// speedup vs baseline: 3.1608x; 1.0210x over previous
#include <cuda_runtime.h>
#include <math.h>
#include <stdint.h>

#define BATCH 8
#define CIN   256
#define NPOS  1568
#define NH    4
#define DH    128
#define O3    1536

// Scratch layouts:
//  pi(k) = ((k&3)<<2)|((k>>2)&3)           (d-dim of Q/K, 16-groups)
//  rho(j) = 4*((j>>1)&3) + 2*(j>>3) + (j&1) (tok-dim of V, 16-groups)
__device__ float g_q[BATCH*NH*NPOS*DH];   // [bh][tok][pi(d)], *scl*log2e, tf32
__device__ float g_k[BATCH*NH*NPOS*DH];   // [bh][tok][pi(d)], emb folded, tf32
__device__ float g_v[BATCH*NH*DH*NPOS];   // [bh][d][rho(tok)], tf32
__device__ float g_wh[O3*CIN];            // tf32(W)
__device__ float g_wl[O3*CIN];            // tf32(W - tf32(W))

__device__ __forceinline__ float to_tf32(float x) {
    uint32_t u; asm("cvt.rna.tf32.f32 %0, %1;" : "=r"(u) : "f"(x));
    return __uint_as_float(u);
}
__device__ __forceinline__ float fast_exp2(float x) {
    float y; asm("ex2.approx.f32 %0, %1;" : "=f"(y) : "f"(x)); return y;
}
__device__ __forceinline__ void mma_tf32(float c[4],
        uint32_t a0, uint32_t a1, uint32_t a2, uint32_t a3,
        uint32_t b0, uint32_t b1) {
    asm volatile(
        "mma.sync.aligned.m16n8k8.row.col.f32.tf32.tf32.f32 "
        "{%0,%1,%2,%3}, {%4,%5,%6,%7}, {%8,%9}, {%0,%1,%2,%3};\n"
        : "+f"(c[0]), "+f"(c[1]), "+f"(c[2]), "+f"(c[3])
        : "r"(a0), "r"(a1), "r"(a2), "r"(a3), "r"(b0), "r"(b1));
}
__device__ __forceinline__ void cp16(uint32_t dst, const void* src, bool ok) {
    unsigned sz = ok ? 16u : 0u;
    asm volatile("cp.async.cg.shared.global [%0], [%1], 16, %2;\n"
                 :: "r"(dst), "l"(src), "r"(sz));
}
#define CP_COMMIT()  asm volatile("cp.async.commit_group;\n")
#define CP_WAIT(N)   asm volatile("cp.async.wait_group %0;\n" :: "n"(N))

// ---------------------------------------------------------------------------
// Kernel W: one-time hi/lo tf32 split of W_qkv (shared by all QKV CTAs).
// ---------------------------------------------------------------------------
__global__ __launch_bounds__(256) void wsplit_kernel(const float* __restrict__ Wq)
{
    int idx = (blockIdx.x * 256 + threadIdx.x) * 4;
    float4 v = *(const float4*)&Wq[idx];
    float hx = to_tf32(v.x), hy = to_tf32(v.y), hz = to_tf32(v.z), hw = to_tf32(v.w);
    *(float4*)&g_wh[idx] = make_float4(hx, hy, hz, hw);
    *(float4*)&g_wl[idx] = make_float4(to_tf32(v.x-hx), to_tf32(v.y-hy),
                                       to_tf32(v.z-hz), to_tf32(v.w-hw));
}

// ---------------------------------------------------------------------------
// Kernel A: QKV projection via 3xTF32 compensated mma GEMM.
// A (pre-split W) arrives via cp.async straight into double-buffered swizzled
// smem; B (fmap) is register-prefetched and split in-kernel.
// ---------------------------------------------------------------------------
__global__ __launch_bounds__(128) void qkv_kernel(
    const float* __restrict__ fmap,
    const float* __restrict__ pf, const float* __restrict__ ph,
    const float* __restrict__ pw)
{
    extern __shared__ float qsm[];
    // [Ah0 0][Al0 4096][Ah1 8192][Al1 12288][Bh 16384][Bl 20480]
    float* Bh = qsm + 16384;
    float* Bl = qsm + 20480;
    float* Ts = qsm;            // 64x65 epilogue overlay

    const int tid  = threadIdx.x;
    const int lane = tid & 31, w = tid >> 5;
    const int gid  = lane >> 2, tig = lane & 3;
    const int row0 = w*16 + gid;
    const int pbase = blockIdx.x * 64;
    const int obase = blockIdx.y * 64;
    const int b     = blockIdx.z;
    const int g4 = gid & 4, g3 = gid & 3, tsw = tig << 3, ksw = gid << 2;
    const int r0 = tid >> 4, c4l = (tid & 15) * 4;
    const uint32_t sbase = (uint32_t)__cvta_generic_to_shared(qsm);

    float acc[8][4];
#pragma unroll
    for (int nb=0;nb<8;nb++)
#pragma unroll
        for (int c=0;c<4;c++) acc[nb][c] = 0.f;

    // cp.async A(ks) -> buffer buf (hi at buf*32768 B, lo at +16384 B)
    auto loadA = [&](int ks, int buf) {
        uint32_t dA = sbase + (uint32_t)buf * 32768u;
#pragma unroll
        for (int p=0;p<8;p++) {
            int r = r0 + p*8;
            uint32_t o = (uint32_t)(r*64 + (c4l ^ ((r&7)<<2))) * 4u;
            const float* srcH = &g_wh[(obase + r)*CIN + ks*64 + c4l];
            const float* srcL = &g_wl[(obase + r)*CIN + ks*64 + c4l];
            cp16(dA + o,          srcH, true);
            cp16(dA + 16384u + o, srcL, true);
        }
    };

    float4 rb[8];
    loadA(0, 0); CP_COMMIT();
#pragma unroll
    for (int p=0;p<8;p++) {
        int r = r0 + p*8;
        rb[p] = make_float4(0.f,0.f,0.f,0.f);
        if (pbase + c4l < NPOS)
            rb[p] = *(const float4*)&fmap[(size_t)(b*CIN + r)*NPOS + pbase + c4l];
    }

    for (int ks = 0; ks < 4; ks++) {
        // split & store B(ks)
#pragma unroll
        for (int p=0;p<8;p++) {
            int r = r0 + p*8;
            float4 v = rb[p];
            float hx = to_tf32(v.x), hy = to_tf32(v.y), hz = to_tf32(v.z), hw = to_tf32(v.w);
            int o = r*64 + (c4l ^ ((r&3)<<3));
            *(float4*)&Bh[o] = make_float4(hx, hy, hz, hw);
            *(float4*)&Bl[o] = make_float4(to_tf32(v.x-hx), to_tf32(v.y-hy),
                                           to_tf32(v.z-hz), to_tf32(v.w-hw));
        }
        CP_WAIT(0);            // A(ks) resident
        __syncthreads();

        if (ks < 3) {
            loadA(ks+1, (ks+1)&1); CP_COMMIT();
            int kn = (ks+1)*64;
#pragma unroll
            for (int p=0;p<8;p++) {
                int r = r0 + p*8;
                rb[p] = make_float4(0.f,0.f,0.f,0.f);
                if (pbase + c4l < NPOS)
                    rb[p] = *(const float4*)&fmap[(size_t)(b*CIN + kn + r)*NPOS + pbase + c4l];
            }
        }

        const float* Ah = qsm + (ks&1)*8192;
        const float* Al = Ah + 4096;
#pragma unroll
        for (int kc=0; kc<8; kc++) {
            int k0 = kc*8;
            uint32_t ah0 = __float_as_uint(Ah[ row0   *64 + (k0^ksw) + tig]);
            uint32_t ah1 = __float_as_uint(Ah[(row0+8)*64 + (k0^ksw) + tig]);
            uint32_t ah2 = __float_as_uint(Ah[ row0   *64 + ((k0+4)^ksw) + tig]);
            uint32_t ah3 = __float_as_uint(Ah[(row0+8)*64 + ((k0+4)^ksw) + tig]);
            uint32_t al0 = __float_as_uint(Al[ row0   *64 + (k0^ksw) + tig]);
            uint32_t al1 = __float_as_uint(Al[(row0+8)*64 + (k0^ksw) + tig]);
            uint32_t al2 = __float_as_uint(Al[ row0   *64 + ((k0+4)^ksw) + tig]);
            uint32_t al3 = __float_as_uint(Al[(row0+8)*64 + ((k0+4)^ksw) + tig]);
#pragma unroll
            for (int nb=0; nb<8; nb++) {
                int cA = ((nb*8+g4)^tsw) + g3;
                uint32_t bh0 = __float_as_uint(Bh[(k0+tig  )*64 + cA]);
                uint32_t bh1 = __float_as_uint(Bh[(k0+tig+4)*64 + cA]);
                uint32_t bl0 = __float_as_uint(Bl[(k0+tig  )*64 + cA]);
                uint32_t bl1 = __float_as_uint(Bl[(k0+tig+4)*64 + cA]);
                mma_tf32(acc[nb], ah0,ah1,ah2,ah3, bl0,bl1);   // hi*lo
                mma_tf32(acc[nb], al0,al1,al2,al3, bh0,bh1);   // lo*hi
                mma_tf32(acc[nb], ah0,ah1,ah2,ah3, bh0,bh1);   // hi*hi
            }
        }
        __syncthreads();
    }

    // scl * log2(e): attention runs in the exp2 domain
    const float scl = 0.08838834764831845f * 1.4426950408889634f;
    const int sec  = obase >> 9;             // 0=q 1=k 2=v (uniform per tile)
    const int head = (obase >> 7) & 3;
    const int d0   = obase & 127;
    const int bh   = b*NH + head;

    if (sec < 2) {
#pragma unroll
        for (int nb=0;nb<8;nb++)
#pragma unroll
            for (int half=0;half<2;half++)
#pragma unroll
                for (int e=0;e<2;e++)
                    Ts[(nb*8 + 2*tig + e)*65 + row0 + half*8] = acc[nb][half*2+e];
    } else {
#pragma unroll
        for (int nb=0;nb<8;nb++)
#pragma unroll
            for (int half=0;half<2;half++)
#pragma unroll
                for (int e=0;e<2;e++)
                    Ts[(row0 + half*8)*65 + nb*8 + 2*tig + e] = acc[nb][half*2+e];
    }
    __syncthreads();

    const int rr  = tid >> 4;
    const int c4  = (tid & 15) * 4;
    const int tq  = (c4 >> 2) & 3;
    const int cb  = c4 & ~15;
    const int lc0 = cb + tq, lc1 = cb + 4 + tq, lc2 = cb + 8 + tq, lc3 = cb + 12 + tq;
    const int lv0 = cb + 2*tq, lv1 = cb + 2*tq + 1, lv2 = cb + 2*tq + 8, lv3 = cb + 2*tq + 9;

#pragma unroll
    for (int pass=0; pass<8; pass++) {
        int r = rr + pass*8;
        if (sec == 2) {
            if (pbase + c4 < NPOS) {
                float v0 = Ts[r*65+lv0], v1 = Ts[r*65+lv1];
                float v2 = Ts[r*65+lv2], v3 = Ts[r*65+lv3];
                *(float4*)&g_v[((size_t)bh*DH + d0 + r)*NPOS + pbase + c4] =
                    make_float4(to_tf32(v0), to_tf32(v1), to_tf32(v2), to_tf32(v3));
            }
        } else {
            float v0 = Ts[r*65+lc0], v1 = Ts[r*65+lc1];
            float v2 = Ts[r*65+lc2], v3 = Ts[r*65+lc3];
            int pos = pbase + r;
            if (pos < NPOS) {
                size_t o_ = ((size_t)bh*NPOS + pos)*DH + d0 + c4;
                if (sec == 0) {
                    *(float4*)&g_q[o_] = make_float4(
                        to_tf32(v0*scl), to_tf32(v1*scl), to_tf32(v2*scl), to_tf32(v3*scl));
                } else {
                    int f_ = pos / 196; int rem = pos - f_*196;
                    int h_ = rem / 14;  int w_  = rem - h_*14;
                    const float* pfr = pf + f_*DH + d0;
                    const float* phr = ph + h_*DH + d0;
                    const float* pwr = pw + w_*DH + d0;
                    *(float4*)&g_k[o_] = make_float4(
                        to_tf32(v0 + pfr[lc0] + phr[lc0] + pwr[lc0]),
                        to_tf32(v1 + pfr[lc1] + phr[lc1] + pwr[lc1]),
                        to_tf32(v2 + pfr[lc2] + phr[lc2] + pwr[lc2]),
                        to_tf32(v3 + pfr[lc3] + phr[lc3] + pwr[lc3]));
                }
            }
        }
    }
}

// ---------------------------------------------------------------------------
// Kernel B: flash attention, Br=128 per CTA (256 threads, 8 warps).
// One K/V stream per SM feeds all 128 q-rows (cp.async traffic halved).
// Fixed-reference-max softmax; S c-frags feed PV directly (sigma/rho layout).
// ---------------------------------------------------------------------------
__global__ __launch_bounds__(256, 1) void attn_kernel(float* __restrict__ out)
{
    extern __shared__ float sm[];
    float* Kb[2] = { sm, sm + 8192 };
    float* Vb    = sm + 16384;         // [d=128][rho(tok)=64]
    float* Od    = sm;                 // 128 x 132 overlay

    const int tid  = threadIdx.x;
    const int lane = tid & 31, w = tid >> 5;
    const int gid  = lane >> 2, tig = lane & 3;
    const int qt = blockIdx.x, bh = blockIdx.y;
    const int qbase = qt * 128;
    const int row0 = w*16 + gid;       // 0..127
    const int gsw = gid << 4;
    const int vsw = (gid & 3) << 4;

    const float* qp = g_q + (size_t)bh * NPOS * DH;
    const float* kp = g_k + (size_t)bh * NPOS * DH;
    const float* vp = g_v + (size_t)bh * DH * NPOS;

    // ---- Q staging through Kb[0], two 64-row passes ----
    uint32_t qa[16][4];
#pragma unroll
    for (int pass = 0; pass < 2; pass++) {
        int r0 = tid >> 5; int c4 = (tid & 31) * 4;
#pragma unroll
        for (int p=0;p<8;p++) {
            int r = r0 + p*8;
            float4 v = make_float4(0.f,0.f,0.f,0.f);
            int grow = qbase + pass*64 + r;
            if (grow < NPOS) v = *(const float4*)&qp[(size_t)grow*DH + c4];
            *(float4*)&Kb[0][r*128 + (c4 ^ ((r&7)<<4))] = v;
        }
        __syncthreads();
        if ((w >> 2) == pass) {
            int lr = row0 & 63;
#pragma unroll
            for (int kpi=0;kpi<8;kpi++) {
                float4 ra = *(const float4*)&Kb[0][ lr   *128 + ((kpi*16) ^ gsw) + tig*4];
                float4 rb = *(const float4*)&Kb[0][(lr+8)*128 + ((kpi*16) ^ gsw) + tig*4];
                qa[2*kpi  ][0] = __float_as_uint(ra.x); qa[2*kpi  ][1] = __float_as_uint(rb.x);
                qa[2*kpi  ][2] = __float_as_uint(ra.y); qa[2*kpi  ][3] = __float_as_uint(rb.y);
                qa[2*kpi+1][0] = __float_as_uint(ra.z); qa[2*kpi+1][1] = __float_as_uint(rb.z);
                qa[2*kpi+1][2] = __float_as_uint(ra.w); qa[2*kpi+1][3] = __float_as_uint(rb.w);
            }
        }
        __syncthreads();
    }

    const uint32_t smK0 = (uint32_t)__cvta_generic_to_shared(Kb[0]);
    const uint32_t smK1 = (uint32_t)__cvta_generic_to_shared(Kb[1]);
    const uint32_t smV  = (uint32_t)__cvta_generic_to_shared(Vb);
    const int lr0 = tid >> 5, lc4 = (tid & 31) * 4;   // K producer (64 rows x 128)
    const int vr0 = tid >> 4, vc4 = (tid & 15) * 4;   // V producer (128 rows x 64)

    // prologue prefetch K(0), V(0)
#pragma unroll
    for (int p=0;p<8;p++) {
        int r = lr0 + p*8;
        cp16(smK0 + (r*128 + (lc4 ^ ((r&7)<<4)))*4, &kp[(size_t)r*DH + lc4], r < NPOS);
    }
    CP_COMMIT();
#pragma unroll
    for (int p=0;p<8;p++) {
        int r = vr0 + p*16;
        cp16(smV + (r*64 + (vc4 ^ ((r&3)<<4)))*4, &vp[(size_t)r*NPOS + vc4], vc4 < NPOS);
    }
    CP_COMMIT();

    float m0 = 0.f, m1 = 0.f;       // fixed per-row reference (set at t==0)
    float l0 = 0.f, l1 = 0.f;       // lane-private partials
    float O[16][4];
#pragma unroll
    for (int nb=0;nb<16;nb++)
#pragma unroll
        for (int c=0;c<4;c++) O[nb][c] = 0.f;

    for (int t = 0; t < 25; t++) {
        const int kb = t * 64;
        const float* Ks = Kb[t & 1];
        CP_WAIT(1);
        __syncthreads();

        float S[8][4];
#pragma unroll
        for (int nb=0;nb<8;nb++)
#pragma unroll
            for (int c=0;c<4;c++) S[nb][c] = 0.f;
#pragma unroll
        for (int kpi=0;kpi<8;kpi++) {
#pragma unroll
            for (int nb=0;nb<8;nb++) {
                int rr = nb*8 + gid;
                float4 kv = *(const float4*)&Ks[rr*128 + ((kpi*16) ^ gsw) + tig*4];
                mma_tf32(S[nb], qa[2*kpi  ][0],qa[2*kpi  ][1],qa[2*kpi  ][2],qa[2*kpi  ][3],
                         __float_as_uint(kv.x), __float_as_uint(kv.y));
                mma_tf32(S[nb], qa[2*kpi+1][0],qa[2*kpi+1][1],qa[2*kpi+1][2],qa[2*kpi+1][3],
                         __float_as_uint(kv.z), __float_as_uint(kv.w));
            }
        }

        {   // prefetch K(t+1) into the other buffer
            int tn = (t+1 < 25) ? t+1 : 24;
            const float* kpn = kp + (size_t)tn*64*DH;
            uint32_t dstK = (t & 1) ? smK0 : smK1;
#pragma unroll
            for (int p=0;p<8;p++) {
                int r = lr0 + p*8;
                cp16(dstK + (r*128 + (lc4 ^ ((r&7)<<4)))*4,
                     &kpn[(size_t)r*DH + lc4], tn*64 + r < NPOS);
            }
            CP_COMMIT();
        }

        if (kb + 64 > NPOS) {
#pragma unroll
            for (int nb=0;nb<8;nb++) {
                int c0 = kb + nb*8 + 2*tig;
                if (c0     >= NPOS) { S[nb][0] = -1e30f; S[nb][2] = -1e30f; }
                if (c0 + 1 >= NPOS) { S[nb][1] = -1e30f; S[nb][3] = -1e30f; }
            }
        }

        if (t == 0) {
            float mx0 = -1e30f, mx1 = -1e30f;
#pragma unroll
            for (int nb=0;nb<8;nb++) {
                mx0 = fmaxf(mx0, fmaxf(S[nb][0], S[nb][1]));
                mx1 = fmaxf(mx1, fmaxf(S[nb][2], S[nb][3]));
            }
            mx0 = fmaxf(mx0, __shfl_xor_sync(0xffffffffu, mx0, 1));
            mx0 = fmaxf(mx0, __shfl_xor_sync(0xffffffffu, mx0, 2));
            mx1 = fmaxf(mx1, __shfl_xor_sync(0xffffffffu, mx1, 1));
            mx1 = fmaxf(mx1, __shfl_xor_sync(0xffffffffu, mx1, 2));
            m0 = mx0; m1 = mx1;
        }

        float rs0 = 0.f, rs1 = 0.f;
#pragma unroll
        for (int nb=0;nb<8;nb++) {
            S[nb][0] = fast_exp2(S[nb][0] - m0); rs0 += S[nb][0];
            S[nb][1] = fast_exp2(S[nb][1] - m0); rs0 += S[nb][1];
            S[nb][2] = fast_exp2(S[nb][2] - m1); rs1 += S[nb][2];
            S[nb][3] = fast_exp2(S[nb][3] - m1); rs1 += S[nb][3];
        }
        l0 += rs0;
        l1 += rs1;

        CP_WAIT(1);
        __syncthreads();

        // ---- O += P V : S c-frags ARE the A-frags (sigma/rho layout) ----
#pragma unroll
        for (int kpi=0;kpi<4;kpi++) {
            int e = 2*kpi, o = 2*kpi+1;
            uint32_t ea0 = __float_as_uint(to_tf32(S[e][0]));
            uint32_t ea1 = __float_as_uint(to_tf32(S[e][2]));
            uint32_t ea2 = __float_as_uint(to_tf32(S[e][1]));
            uint32_t ea3 = __float_as_uint(to_tf32(S[e][3]));
            uint32_t oa0 = __float_as_uint(to_tf32(S[o][0]));
            uint32_t oa1 = __float_as_uint(to_tf32(S[o][2]));
            uint32_t oa2 = __float_as_uint(to_tf32(S[o][1]));
            uint32_t oa3 = __float_as_uint(to_tf32(S[o][3]));
#pragma unroll
            for (int nb=0;nb<16;nb++) {
                int rr = nb*8 + gid;
                float4 vv = *(const float4*)&Vb[rr*64 + ((kpi*16) ^ vsw) + tig*4];
                mma_tf32(O[nb], ea0,ea1,ea2,ea3,
                         __float_as_uint(vv.x), __float_as_uint(vv.y));
                mma_tf32(O[nb], oa0,oa1,oa2,oa3,
                         __float_as_uint(vv.z), __float_as_uint(vv.w));
            }
        }
        __syncthreads();

        {   // prefetch V(t+1)
            int tn = (t+1 < 25) ? t+1 : 24;
            const float* vpn = vp + (size_t)tn*64;
#pragma unroll
            for (int p=0;p<8;p++) {
                int r = vr0 + p*16;
                cp16(smV + (r*64 + (vc4 ^ ((r&3)<<4)))*4,
                     &vpn[(size_t)r*NPOS + vc4], tn*64 + vc4 < NPOS);
            }
            CP_COMMIT();
        }
    }

    // one-time l reduction across the quad
    l0 += __shfl_xor_sync(0xffffffffu, l0, 1);
    l0 += __shfl_xor_sync(0xffffffffu, l0, 2);
    l1 += __shfl_xor_sync(0xffffffffu, l1, 1);
    l1 += __shfl_xor_sync(0xffffffffu, l1, 2);

    CP_WAIT(0);
    __syncthreads();
    float inv0 = 1.0f / l0, inv1 = 1.0f / l1;
#pragma unroll
    for (int nb=0;nb<16;nb++) {
        Od[(nb*8 + 2*tig    )*132 + row0    ] = O[nb][0] * inv0;
        Od[(nb*8 + 2*tig + 1)*132 + row0    ] = O[nb][1] * inv0;
        Od[(nb*8 + 2*tig    )*132 + row0 + 8] = O[nb][2] * inv1;
        Od[(nb*8 + 2*tig + 1)*132 + row0 + 8] = O[nb][3] * inv1;
    }
    __syncthreads();

    const int b = bh >> 2, head = bh & 3;
    const size_t ch0 = (size_t)b*512 + head*128;
    {
        int t2 = (tid & 63) * 2;
#pragma unroll
        for (int p=0;p<32;p++) {
            int dd = (tid >> 6) + p*4;
            if (qbase + t2 < NPOS) {
                float2 v = *(const float2*)&Od[dd*132 + t2];
                *(float2*)&out[(ch0 + dd)*NPOS + qbase + t2] = v;
            }
        }
    }
}

// ---------------------------------------------------------------------------
extern "C" void kernel_launch(void* const* d_in, const int* in_sizes, int n_in,
                              void* d_out, int out_size)
{
    const float* fmap = (const float*)d_in[0];
    const float* Wq   = (const float*)d_in[1];
    const float* pf   = (const float*)d_in[2];
    const float* ph   = (const float*)d_in[3];
    const float* pw   = (const float*)d_in[4];
    float* out = (float*)d_out;

    wsplit_kernel<<<O3*CIN/1024, 256>>>(Wq);

    const size_t smemA = (size_t)24576 * sizeof(float);   // 96 KB
    cudaFuncSetAttribute(qkv_kernel, cudaFuncAttributeMaxDynamicSharedMemorySize,
                         (int)smemA);
    dim3 gA(25, 24, BATCH);
    qkv_kernel<<<gA, 128, smemA>>>(fmap, pf, ph, pw);

    const size_t smemB = (size_t)24576 * sizeof(float);   // 96 KB
    cudaFuncSetAttribute(attn_kernel, cudaFuncAttributeMaxDynamicSharedMemorySize,
                         (int)smemB);
    dim3 gB(13, 32);
    attn_kernel<<<gB, 256, smemB>>>(out);
}